// round 1
// baseline (speedup 1.0000x reference)
#include <cuda_runtime.h>

#define BB 16
#define NN 4096
#define CC 256

// Scratch (device globals — no allocation allowed)
__device__ float g_q[(size_t)BB*CC*NN];     // q = Wq @ xc   [B][C][N]
__device__ float g_v[(size_t)BB*CC*NN];     // v = Wv @ xc + bv
__device__ float g_u[(size_t)BB*CC*NN];     // u = Wt @ xc
__device__ float g_t[(size_t)BB*CC*NN];     // t (pre-BN)
__device__ float g_att[(size_t)BB*CC*CC];   // energy -> softmax att
__device__ float g_M[(size_t)BB*CC*CC];     // M[b] = Wt @ att_norm[b]^T
__device__ float g_colsum[BB*CC];
__device__ float g_mean[CC];
__device__ float g_rstd[CC];

// ---------------------------------------------------------------------------
// K1: q/v/u = W @ xc where xc[b,c,n] = x[b,n,c].  out[b,o,n] = sum_c W[o,c]*x[b,n,c]
// grid (N/64, C/64, 3*B), block 256. 64x64 tile, 4x4 per thread, K-chunk 16.
// ---------------------------------------------------------------------------
__global__ void k_qvu(const float* __restrict__ x, const float* __restrict__ Wq,
                      const float* __restrict__ Wv, const float* __restrict__ Wt,
                      const float* __restrict__ bv) {
    int which = blockIdx.z / BB;
    int b     = blockIdx.z % BB;
    const float* W = (which == 0) ? Wq : (which == 1) ? Wv : Wt;
    float* out     = (which == 0) ? g_q : (which == 1) ? g_v : g_u;
    int oBase = blockIdx.y * 64;
    int nBase = blockIdx.x * 64;
    __shared__ float Ws[16][65];   // [k][o]
    __shared__ float Xs[64][17];   // [n][k]
    int t  = threadIdx.x;
    int tx = t & 15, ty = t >> 4;
    float acc[4][4] = {};
    const float* xb = x + (size_t)b * NN * CC;
    for (int c0 = 0; c0 < CC; c0 += 16) {
        #pragma unroll
        for (int j = 0; j < 4; j++) {
            int idx = t + j * 256;
            int o = idx >> 4, k = idx & 15;
            Ws[k][o] = W[(size_t)(oBase + o) * CC + c0 + k];
        }
        {
            int n = t >> 2, cg = (t & 3) * 4;
            float4 v4 = *(const float4*)(xb + (size_t)(nBase + n) * CC + c0 + cg);
            Xs[n][cg + 0] = v4.x; Xs[n][cg + 1] = v4.y;
            Xs[n][cg + 2] = v4.z; Xs[n][cg + 3] = v4.w;
        }
        __syncthreads();
        #pragma unroll
        for (int k = 0; k < 16; k++) {
            float a[4], bx[4];
            #pragma unroll
            for (int i = 0; i < 4; i++) a[i] = Ws[k][ty * 4 + i];
            #pragma unroll
            for (int j = 0; j < 4; j++) bx[j] = Xs[tx * 4 + j][k];
            #pragma unroll
            for (int i = 0; i < 4; i++)
                #pragma unroll
                for (int j = 0; j < 4; j++)
                    acc[i][j] = fmaf(a[i], bx[j], acc[i][j]);
        }
        __syncthreads();
    }
    #pragma unroll
    for (int i = 0; i < 4; i++) {
        int o = oBase + ty * 4 + i;
        float bias = (which == 1) ? bv[o] : 0.0f;
        size_t row = ((size_t)b * CC + o) * NN + nBase;
        #pragma unroll
        for (int j = 0; j < 4; j++)
            out[row + tx * 4 + j] = acc[i][j] + bias;
    }
}

// ---------------------------------------------------------------------------
// K2: energy[b,c,d] = sum_n q[b,c,n]*q[b,d,n]   (Gram, K=4096)
// grid (4,4,B), block 256
// ---------------------------------------------------------------------------
__global__ void k_gram() {
    int b = blockIdx.z;
    int cBase = blockIdx.y * 64, dBase = blockIdx.x * 64;
    __shared__ float Qc[64][17], Qd[64][17];
    int t = threadIdx.x, tx = t & 15, ty = t >> 4;
    float acc[4][4] = {};
    const float* qb = g_q + (size_t)b * CC * NN;
    for (int n0 = 0; n0 < NN; n0 += 16) {
        #pragma unroll
        for (int j = 0; j < 4; j++) {
            int idx = t + j * 256;
            int r = idx >> 4, k = idx & 15;
            Qc[r][k] = qb[(size_t)(cBase + r) * NN + n0 + k];
            Qd[r][k] = qb[(size_t)(dBase + r) * NN + n0 + k];
        }
        __syncthreads();
        #pragma unroll
        for (int k = 0; k < 16; k++) {
            float a[4], d[4];
            #pragma unroll
            for (int i = 0; i < 4; i++) a[i] = Qc[ty * 4 + i][k];
            #pragma unroll
            for (int j = 0; j < 4; j++) d[j] = Qd[tx * 4 + j][k];
            #pragma unroll
            for (int i = 0; i < 4; i++)
                #pragma unroll
                for (int j = 0; j < 4; j++)
                    acc[i][j] = fmaf(a[i], d[j], acc[i][j]);
        }
        __syncthreads();
    }
    #pragma unroll
    for (int i = 0; i < 4; i++)
        #pragma unroll
        for (int j = 0; j < 4; j++)
            g_att[((size_t)b * CC + cBase + ty * 4 + i) * CC + dBase + tx * 4 + j] = acc[i][j];
}

// ---------------------------------------------------------------------------
// K3: row softmax over d (axis=-1). grid B*C, block 256 (= C)
// ---------------------------------------------------------------------------
__global__ void k_softmax() {
    size_t row = blockIdx.x;
    float* p = g_att + row * CC;
    int t = threadIdx.x;
    float v = p[t];
    __shared__ float red[256];
    red[t] = v; __syncthreads();
    for (int s = 128; s > 0; s >>= 1) { if (t < s) red[t] = fmaxf(red[t], red[t + s]); __syncthreads(); }
    float mx = red[0]; __syncthreads();
    float e = __expf(v - mx);
    red[t] = e; __syncthreads();
    for (int s = 128; s > 0; s >>= 1) { if (t < s) red[t] += red[t + s]; __syncthreads(); }
    p[t] = e / red[0];
}

// K4: colsum[b,d] = sum_c att[b,c,d]. grid B, block 256
__global__ void k_colsum() {
    int b = blockIdx.x, d = threadIdx.x;
    float s = 0.f;
    for (int c = 0; c < CC; c++) s += g_att[((size_t)b * CC + c) * CC + d];
    g_colsum[b * CC + d] = s;
}

// ---------------------------------------------------------------------------
// K5: M[b,o,c2] = sum_c (Wt[o,c]/(1e-9+colsum[b,c])) * att[b,c2,c]
// grid (4,4,B), block 256
// ---------------------------------------------------------------------------
__global__ void k_mgemm(const float* __restrict__ Wt) {
    int b = blockIdx.z;
    int oBase = blockIdx.y * 64, c2Base = blockIdx.x * 64;
    __shared__ float As[64][17], Bs[64][17];
    int t = threadIdx.x, tx = t & 15, ty = t >> 4;
    float acc[4][4] = {};
    for (int c0 = 0; c0 < CC; c0 += 16) {
        #pragma unroll
        for (int j = 0; j < 4; j++) {
            int idx = t + j * 256;
            int r = idx >> 4, k = idx & 15;
            As[r][k] = Wt[(size_t)(oBase + r) * CC + c0 + k]
                       / (1e-9f + g_colsum[b * CC + c0 + k]);
            Bs[r][k] = g_att[((size_t)b * CC + c2Base + r) * CC + c0 + k];
        }
        __syncthreads();
        #pragma unroll
        for (int k = 0; k < 16; k++) {
            float a[4], d[4];
            #pragma unroll
            for (int i = 0; i < 4; i++) a[i] = As[ty * 4 + i][k];
            #pragma unroll
            for (int j = 0; j < 4; j++) d[j] = Bs[tx * 4 + j][k];
            #pragma unroll
            for (int i = 0; i < 4; i++)
                #pragma unroll
                for (int j = 0; j < 4; j++)
                    acc[i][j] = fmaf(a[i], d[j], acc[i][j]);
        }
        __syncthreads();
    }
    #pragma unroll
    for (int i = 0; i < 4; i++)
        #pragma unroll
        for (int j = 0; j < 4; j++)
            g_M[((size_t)b * CC + oBase + ty * 4 + i) * CC + c2Base + tx * 4 + j] = acc[i][j];
}

// ---------------------------------------------------------------------------
// K6: t[b,o,n] = u[b,o,n] + bt[o] - sum_c M[b,o,c]*v[b,c,n]
// grid (64,4,B), block 256
// ---------------------------------------------------------------------------
__global__ void k_tgemm(const float* __restrict__ bt) {
    int b = blockIdx.z;
    int oBase = blockIdx.y * 64, nBase = blockIdx.x * 64;
    __shared__ float Ms[16][65];   // [k][o]
    __shared__ float Vs[16][65];   // [k][n]
    int t = threadIdx.x, tx = t & 15, ty = t >> 4;
    float acc[4][4] = {};
    const float* Mb = g_M + (size_t)b * CC * CC;
    const float* vb = g_v + (size_t)b * CC * NN;
    for (int c0 = 0; c0 < CC; c0 += 16) {
        #pragma unroll
        for (int j = 0; j < 4; j++) {
            int idx = t + j * 256;
            { int o = idx >> 4, k = idx & 15;
              Ms[k][o] = Mb[(size_t)(oBase + o) * CC + c0 + k]; }
            { int k = idx >> 6, n = idx & 63;
              Vs[k][n] = vb[(size_t)(c0 + k) * NN + nBase + n]; }
        }
        __syncthreads();
        #pragma unroll
        for (int k = 0; k < 16; k++) {
            float a[4], d[4];
            #pragma unroll
            for (int i = 0; i < 4; i++) a[i] = Ms[k][ty * 4 + i];
            #pragma unroll
            for (int j = 0; j < 4; j++) d[j] = Vs[k][tx * 4 + j];
            #pragma unroll
            for (int i = 0; i < 4; i++)
                #pragma unroll
                for (int j = 0; j < 4; j++)
                    acc[i][j] = fmaf(a[i], d[j], acc[i][j]);
        }
        __syncthreads();
    }
    #pragma unroll
    for (int i = 0; i < 4; i++) {
        int o = oBase + ty * 4 + i;
        float bo = bt[o];
        #pragma unroll
        for (int j = 0; j < 4; j++) {
            size_t idx = ((size_t)b * CC + o) * NN + nBase + tx * 4 + j;
            g_t[idx] = g_u[idx] + bo - acc[i][j];
        }
    }
}

// K7: BN batch stats per channel. grid C, block 256
__global__ void k_bnstats() {
    int o = blockIdx.x, t = threadIdx.x;
    float s = 0.f, sq = 0.f;
    for (int b = 0; b < BB; b++) {
        const float* p = g_t + ((size_t)b * CC + o) * NN;
        for (int n = t; n < NN; n += 256) { float v = p[n]; s += v; sq += v * v; }
    }
    __shared__ float rs[256], rq[256];
    rs[t] = s; rq[t] = sq; __syncthreads();
    for (int st = 128; st > 0; st >>= 1) {
        if (t < st) { rs[t] += rs[t + st]; rq[t] += rq[t + st]; }
        __syncthreads();
    }
    if (t == 0) {
        float inv = 1.0f / (float)(BB * NN);
        float mean = rs[0] * inv;
        float var  = rq[0] * inv - mean * mean;
        g_mean[o] = mean;
        g_rstd[o] = rsqrtf(var + 1e-5f);
    }
}

// ---------------------------------------------------------------------------
// K8: out[b,n,o] = x[b,n,o] + relu(gamma*(t-mean)*rstd + beta)  (32x32 smem transpose)
// grid (N/32, C/32, B), block 256
// ---------------------------------------------------------------------------
__global__ void k_final(const float* __restrict__ x, const float* __restrict__ gamma,
                        const float* __restrict__ beta, float* __restrict__ out) {
    int b = blockIdx.z;
    int oBase = blockIdx.y * 32, nBase = blockIdx.x * 32;
    __shared__ float ts[32][33];
    int t = threadIdx.x;
    int ln = t & 31, wr = t >> 5;    // ln: fast dim, wr: 0..7
    #pragma unroll
    for (int r = 0; r < 4; r++) {
        int o = oBase + wr + r * 8;
        ts[wr + r * 8][ln] = g_t[((size_t)b * CC + o) * NN + nBase + ln];
    }
    __syncthreads();
    int o = oBase + ln;
    float g = gamma[o], be = beta[o], mn = g_mean[o], rsd = g_rstd[o];
    #pragma unroll
    for (int r = 0; r < 4; r++) {
        int n = nBase + wr + r * 8;
        float tv  = ts[ln][wr + r * 8];
        float val = fmaxf(fmaf(g * rsd, tv - mn, be), 0.0f);
        size_t oi = ((size_t)b * NN + n) * CC + o;
        out[oi] = x[oi] + val;
    }
}

extern "C" void kernel_launch(void* const* d_in, const int* in_sizes, int n_in,
                              void* d_out, int out_size) {
    (void)in_sizes; (void)n_in; (void)out_size;
    const float* x     = (const float*)d_in[1];
    const float* Wq    = (const float*)d_in[2];
    const float* Wv    = (const float*)d_in[3];
    const float* bv    = (const float*)d_in[4];
    const float* Wt    = (const float*)d_in[5];
    const float* bt    = (const float*)d_in[6];
    const float* gamma = (const float*)d_in[7];
    const float* beta  = (const float*)d_in[8];
    float* out = (float*)d_out;

    k_qvu    <<<dim3(NN/64, CC/64, 3*BB), 256>>>(x, Wq, Wv, Wt, bv);
    k_gram   <<<dim3(CC/64, CC/64, BB),   256>>>();
    k_softmax<<<BB*CC,                    256>>>();
    k_colsum <<<BB,                       256>>>();
    k_mgemm  <<<dim3(CC/64, CC/64, BB),   256>>>(Wt);
    k_tgemm  <<<dim3(NN/64, CC/64, BB),   256>>>(bt);
    k_bnstats<<<CC,                       256>>>();
    k_final  <<<dim3(NN/32, CC/32, BB),   256>>>(x, gamma, beta, out);
}

// round 3
// speedup vs baseline: 1.9506x; 1.9506x over previous
#include <cuda_runtime.h>
#include <cuda_bf16.h>
#include <cstdint>

#define BB 16
#define NN 4096
#define CC 256

using bf16 = __nv_bfloat16;

// ---------------- scratch (device globals; no allocation allowed) ----------
__device__ bf16  g_xhi[(size_t)BB*NN*CC];   // x split bf16, [B][N][C]
__device__ bf16  g_xlo[(size_t)BB*NN*CC];
__device__ bf16  g_qhi[(size_t)BB*CC*NN];   // q, [B][C][N]
__device__ bf16  g_qlo[(size_t)BB*CC*NN];
__device__ bf16  g_vhi[(size_t)BB*NN*CC];   // v^T, [B][N][C]
__device__ bf16  g_vlo[(size_t)BB*NN*CC];
__device__ bf16  g_Whi[3*CC*CC];            // Wq, Wv, Wt split
__device__ bf16  g_Wlo[3*CC*CC];
__device__ float g_u[(size_t)BB*NN*CC];     // Wt@xc in [B][N][C]
__device__ float g_t[(size_t)BB*NN*CC];     // pre-BN t in [B][N][C]
__device__ float g_att[(size_t)BB*CC*CC];   // energy -> softmax att
__device__ bf16  g_Mhi[(size_t)BB*CC*CC];   // M[b][o][c] split
__device__ bf16  g_Mlo[(size_t)BB*CC*CC];
__device__ float g_colsum[BB*CC];
__device__ float g_ps[512*CC];
__device__ float g_pq[512*CC];
__device__ float g_scale[CC];
__device__ float g_shift[CC];

#define SDYN 65536

// ---------------- helpers ---------------------------------------------------
__device__ __forceinline__ uint32_t smem_u32(const void* p){
    uint32_t a;
    asm("{ .reg .u64 t; cvta.to.shared.u64 t, %1; cvt.u32.u64 %0, t; }" : "=r"(a) : "l"(p));
    return a;
}
__device__ __forceinline__ uint32_t sw128(uint32_t o){ return o ^ ((o >> 3) & 0x70); }

__device__ __forceinline__ void ldm4(uint32_t* r, uint32_t addr){
    asm volatile("ldmatrix.sync.aligned.m8n8.x4.shared.b16 {%0,%1,%2,%3}, [%4];"
        : "=r"(r[0]), "=r"(r[1]), "=r"(r[2]), "=r"(r[3]) : "r"(addr));
}
__device__ __forceinline__ void mma_bf16(float* c, const uint32_t* a, const uint32_t* b){
    asm volatile("mma.sync.aligned.m16n8k16.row.col.f32.bf16.bf16.f32 "
        "{%0,%1,%2,%3}, {%4,%5,%6,%7}, {%8,%9}, {%0,%1,%2,%3};"
        : "+f"(c[0]), "+f"(c[1]), "+f"(c[2]), "+f"(c[3])
        : "r"(a[0]), "r"(a[1]), "r"(a[2]), "r"(a[3]), "r"(b[0]), "r"(b[1]));
}
__device__ __forceinline__ void split_store(bf16* hi, bf16* lo, size_t i, float v){
    bf16 h = __float2bfloat16(v);
    hi[i] = h;
    lo[i] = __float2bfloat16(v - __bfloat162float(h));
}
__device__ __forceinline__ uint32_t pack2(float v0, float v1){
    __nv_bfloat162 p = __floats2bfloat162_rn(v0, v1);  // (v0 -> x, v1 -> y)
    return *(uint32_t*)&p;
}
__device__ __forceinline__ void split_pair(float v0, float v1, uint32_t& hi, uint32_t& lo){
    bf16 h0 = __float2bfloat16(v0), h1 = __float2bfloat16(v1);
    float r0 = v0 - __bfloat162float(h0), r1 = v1 - __bfloat162float(h1);
    __nv_bfloat162 ph; ph.x = h0; ph.y = h1;
    __nv_bfloat162 pl = __floats2bfloat162_rn(r0, r1);
    hi = *(uint32_t*)&ph;
    lo = *(uint32_t*)&pl;
}

// ---------------------------------------------------------------------------
// Split-bf16 128x128 GEMM mainloop, mma.sync.m16n8k16.
// A: M-rows K-major (ldA), B: N-rows K-major (ldB), both hi/lo.
// acc += Ahi*Bhi + Ahi*Blo + Alo*Bhi. 256 threads, warp grid 4(M) x 2(N).
// smem: Ahi@0, Alo@16K, Bhi@32K, Blo@48K; rows of 64 bf16 (128B), SW128.
// ---------------------------------------------------------------------------
__device__ __forceinline__ void gemm_main(char* smem,
        const bf16* __restrict__ Ahi, const bf16* __restrict__ Alo, int ldA,
        const bf16* __restrict__ Bhi, const bf16* __restrict__ Blo, int ldB,
        int nChunks, float acc[2][8][4])
{
    int tid = threadIdx.x, lane = tid & 31, wid = tid >> 5;
    int warpM = wid & 3, warpN = wid >> 2;
    uint32_t sb = smem_u32(smem);

    for (int cc = 0; cc < nChunks; cc++){
        int c0 = cc * 64;
        #pragma unroll
        for (int i = 0; i < 4; i++){
            int g = tid + i * 256;            // 0..1023
            int row = g >> 3, cg = g & 7;
            uint32_t so = sw128((uint32_t)(row * 128 + cg * 16));
            size_t ga = (size_t)row * ldA + c0 + cg * 8;
            size_t gb = (size_t)row * ldB + c0 + cg * 8;
            *(uint4*)(smem + so)         = *(const uint4*)(Ahi + ga);
            *(uint4*)(smem + 16384 + so) = *(const uint4*)(Alo + ga);
            *(uint4*)(smem + 32768 + so) = *(const uint4*)(Bhi + gb);
            *(uint4*)(smem + 49152 + so) = *(const uint4*)(Blo + gb);
        }
        __syncthreads();
        #pragma unroll
        for (int ks = 0; ks < 4; ks++){
            uint32_t ahi[2][4], alo[2][4];
            #pragma unroll
            for (int mf = 0; mf < 2; mf++){
                int row = warpM * 32 + mf * 16 + (lane & 15);
                uint32_t off = sw128((uint32_t)(row * 128 + ks * 32 + (lane >> 4) * 16));
                ldm4(ahi[mf], sb + off);
                ldm4(alo[mf], sb + 16384 + off);
            }
            #pragma unroll
            for (int ng = 0; ng < 4; ng++){
                int rowb = warpN * 64 + ng * 16 + (lane & 15);
                uint32_t off = sw128((uint32_t)(rowb * 128 + ks * 32 + (lane >> 4) * 16));
                uint32_t bh[4], bl[4];
                ldm4(bh, sb + 32768 + off);
                ldm4(bl, sb + 49152 + off);
                uint32_t bh0[2] = {bh[0], bh[2]}, bh1[2] = {bh[1], bh[3]};
                uint32_t bl0[2] = {bl[0], bl[2]}, bl1[2] = {bl[1], bl[3]};
                #pragma unroll
                for (int mf = 0; mf < 2; mf++){
                    mma_bf16(acc[mf][ng*2],     ahi[mf], bh0);
                    mma_bf16(acc[mf][ng*2],     ahi[mf], bl0);
                    mma_bf16(acc[mf][ng*2],     alo[mf], bh0);
                    mma_bf16(acc[mf][ng*2 + 1], ahi[mf], bh1);
                    mma_bf16(acc[mf][ng*2 + 1], ahi[mf], bl1);
                    mma_bf16(acc[mf][ng*2 + 1], alo[mf], bh1);
                }
            }
        }
        __syncthreads();
    }
}

// ---------------- conversion kernels ---------------------------------------
__global__ void k_cvt_x(const float* __restrict__ x){
    size_t i = ((size_t)blockIdx.x * blockDim.x + threadIdx.x) * 4;
    float4 v = *(const float4*)(x + i);
    float vv[4] = {v.x, v.y, v.z, v.w};
    #pragma unroll
    for (int j = 0; j < 4; j++) split_store(g_xhi, g_xlo, i + j, vv[j]);
}
__global__ void k_cvt_w(const float* __restrict__ Wq, const float* __restrict__ Wv,
                        const float* __restrict__ Wt){
    int idx = blockIdx.x * blockDim.x + threadIdx.x;
    int which = idx >> 16, rem = idx & 65535;
    const float* s = (which == 0) ? Wq : (which == 1) ? Wv : Wt;
    split_store(g_Whi, g_Wlo, idx, s[rem]);
}

// ---------------- KT1: q / vT / u -----------------------------------------
__global__ void __launch_bounds__(256)
kt1(const float* __restrict__ bv){
    extern __shared__ char smem[];
    int which = blockIdx.z >> 4, b = blockIdx.z & 15;
    size_t xoff = (size_t)b * NN * CC;
    const bf16 *Ahi, *Alo, *Bhi, *Blo;
    int mBase, nBase;
    if (which == 0){
        mBase = blockIdx.y * 128; nBase = blockIdx.x * 128;
        Ahi = g_Whi + mBase * CC;                Alo = g_Wlo + mBase * CC;
        Bhi = g_xhi + xoff + (size_t)nBase * CC; Blo = g_xlo + xoff + (size_t)nBase * CC;
    } else {
        mBase = blockIdx.x * 128; nBase = blockIdx.y * 128;
        Ahi = g_xhi + xoff + (size_t)mBase * CC; Alo = g_xlo + xoff + (size_t)mBase * CC;
        int w = which * CC * CC;
        Bhi = g_Whi + w + nBase * CC;            Blo = g_Wlo + w + nBase * CC;
    }
    float acc[2][8][4] = {};
    gemm_main(smem, Ahi, Alo, CC, Bhi, Blo, CC, 4, acc);

    int tid = threadIdx.x, lane = tid & 31, wid = tid >> 5;
    int warpM = wid & 3, warpN = wid >> 2;
    int gr = lane >> 2, gc = (lane & 3) * 2;
    #pragma unroll
    for (int mf = 0; mf < 2; mf++){
        #pragma unroll
        for (int nf = 0; nf < 8; nf++){
            float* c = acc[mf][nf];
            int row0 = warpM * 32 + mf * 16 + gr;
            int col  = warpN * 64 + nf * 8 + gc;
            #pragma unroll
            for (int h = 0; h < 2; h++){
                int row = row0 + h * 8;
                float v0 = c[2*h], v1 = c[2*h + 1];
                if (which == 0){
                    int o = mBase + row, n = nBase + col;
                    size_t di = ((size_t)b * CC + o) * NN + n;
                    uint32_t hi, lo;
                    split_pair(v0, v1, hi, lo);
                    *(uint32_t*)(g_qhi + di) = hi;
                    *(uint32_t*)(g_qlo + di) = lo;
                } else {
                    int n = mBase + row, o = nBase + col;
                    size_t di = ((size_t)b * NN + n) * CC + o;
                    if (which == 1){
                        uint32_t hi, lo;
                        split_pair(v0 + bv[o], v1 + bv[o + 1], hi, lo);
                        *(uint32_t*)(g_vhi + di) = hi;
                        *(uint32_t*)(g_vlo + di) = lo;
                    } else {
                        *(float2*)(g_u + di) = make_float2(v0, v1);
                    }
                }
            }
        }
    }
}

// ---------------- KT2: energy = q . q^T (K = 4096) -------------------------
__global__ void __launch_bounds__(256)
kt2(){
    extern __shared__ char smem[];
    int b = blockIdx.z;
    int cBase = blockIdx.y * 128, dBase = blockIdx.x * 128;
    const bf16* Ah = g_qhi + ((size_t)b * CC + cBase) * NN;
    const bf16* Al = g_qlo + ((size_t)b * CC + cBase) * NN;
    const bf16* Bh = g_qhi + ((size_t)b * CC + dBase) * NN;
    const bf16* Bl = g_qlo + ((size_t)b * CC + dBase) * NN;
    float acc[2][8][4] = {};
    gemm_main(smem, Ah, Al, NN, Bh, Bl, NN, NN / 64, acc);

    int tid = threadIdx.x, lane = tid & 31, wid = tid >> 5;
    int warpM = wid & 3, warpN = wid >> 2;
    int gr = lane >> 2, gc = (lane & 3) * 2;
    #pragma unroll
    for (int mf = 0; mf < 2; mf++)
        #pragma unroll
        for (int nf = 0; nf < 8; nf++){
            float* c = acc[mf][nf];
            int row0 = warpM * 32 + mf * 16 + gr;
            int col  = warpN * 64 + nf * 8 + gc;
            #pragma unroll
            for (int h = 0; h < 2; h++){
                int cc_ = cBase + row0 + h * 8, d = dBase + col;
                *(float2*)(g_att + ((size_t)b * CC + cc_) * CC + d)
                    = make_float2(c[2*h], c[2*h + 1]);
            }
        }
}

// ---------------- softmax / colsum / M -------------------------------------
__global__ void k_softmax(){
    size_t row = blockIdx.x;
    float* p = g_att + row * CC;
    int t = threadIdx.x;
    float v = p[t];
    __shared__ float red[256];
    red[t] = v; __syncthreads();
    for (int s = 128; s > 0; s >>= 1){ if (t < s) red[t] = fmaxf(red[t], red[t+s]); __syncthreads(); }
    float mx = red[0]; __syncthreads();
    float e = __expf(v - mx);
    red[t] = e; __syncthreads();
    for (int s = 128; s > 0; s >>= 1){ if (t < s) red[t] += red[t+s]; __syncthreads(); }
    p[t] = e / red[0];
}
__global__ void k_colsum(){
    int b = blockIdx.x, d = threadIdx.x;
    float s = 0.f;
    for (int c = 0; c < CC; c++) s += g_att[((size_t)b * CC + c) * CC + d];
    g_colsum[b * CC + d] = s;
}
__global__ void k_mgemm(const float* __restrict__ Wt){
    int b = blockIdx.z;
    int oBase = blockIdx.y * 64, c2Base = blockIdx.x * 64;
    __shared__ float As[64][17], Bs[64][17];
    int t = threadIdx.x, tx = t & 15, ty = t >> 4;
    float acc[4][4] = {};
    for (int c0 = 0; c0 < CC; c0 += 16){
        #pragma unroll
        for (int j = 0; j < 4; j++){
            int idx = t + j * 256;
            int r = idx >> 4, k = idx & 15;
            As[r][k] = Wt[(size_t)(oBase + r) * CC + c0 + k]
                       / (1e-9f + g_colsum[b * CC + c0 + k]);
            Bs[r][k] = g_att[((size_t)b * CC + c2Base + r) * CC + c0 + k];
        }
        __syncthreads();
        #pragma unroll
        for (int k = 0; k < 16; k++){
            float a[4], d[4];
            #pragma unroll
            for (int i = 0; i < 4; i++) a[i] = As[ty*4+i][k];
            #pragma unroll
            for (int j = 0; j < 4; j++) d[j] = Bs[tx*4+j][k];
            #pragma unroll
            for (int i = 0; i < 4; i++)
                #pragma unroll
                for (int j = 0; j < 4; j++)
                    acc[i][j] = fmaf(a[i], d[j], acc[i][j]);
        }
        __syncthreads();
    }
    #pragma unroll
    for (int i = 0; i < 4; i++)
        #pragma unroll
        for (int j = 0; j < 4; j++)
            split_store(g_Mhi, g_Mlo,
                ((size_t)b * CC + oBase + ty*4 + i) * CC + c2Base + tx*4 + j, acc[i][j]);
}

// ---------------- KT6: t[n,o] = u + bt - vT . M^T --------------------------
__global__ void __launch_bounds__(256)
kt6(const float* __restrict__ bt){
    extern __shared__ char smem[];
    int b = blockIdx.z;
    int mBase = blockIdx.x * 128;   // n
    int oBase = blockIdx.y * 128;   // o
    const bf16* Ah = g_vhi + ((size_t)b * NN + mBase) * CC;
    const bf16* Al = g_vlo + ((size_t)b * NN + mBase) * CC;
    const bf16* Bh = g_Mhi + ((size_t)b * CC + oBase) * CC;
    const bf16* Bl = g_Mlo + ((size_t)b * CC + oBase) * CC;
    float acc[2][8][4] = {};
    gemm_main(smem, Ah, Al, CC, Bh, Bl, CC, 4, acc);

    int tid = threadIdx.x, lane = tid & 31, wid = tid >> 5;
    int warpM = wid & 3, warpN = wid >> 2;
    int gr = lane >> 2, gc = (lane & 3) * 2;
    #pragma unroll
    for (int mf = 0; mf < 2; mf++)
        #pragma unroll
        for (int nf = 0; nf < 8; nf++){
            float* c = acc[mf][nf];
            int row0 = warpM * 32 + mf * 16 + gr;
            int col  = warpN * 64 + nf * 8 + gc;
            #pragma unroll
            for (int h = 0; h < 2; h++){
                int n = mBase + row0 + h * 8, o = oBase + col;
                size_t di = ((size_t)b * NN + n) * CC + o;
                float2 u2 = *(const float2*)(g_u + di);
                *(float2*)(g_t + di) = make_float2(u2.x + bt[o]     - c[2*h],
                                                   u2.y + bt[o + 1] - c[2*h + 1]);
            }
        }
}

// ---------------- BN stats + final -----------------------------------------
__global__ void k_bnpart(){
    int blk = blockIdx.x, o = threadIdx.x;
    const float* base = g_t + (size_t)blk * 128 * CC + o;
    float s = 0.f, q = 0.f;
    #pragma unroll 4
    for (int r = 0; r < 128; r++){ float v = base[(size_t)r * CC]; s += v; q += v * v; }
    g_ps[blk * CC + o] = s;
    g_pq[blk * CC + o] = q;
}
__global__ void k_bnfin(const float* __restrict__ gamma, const float* __restrict__ beta){
    int o = blockIdx.x, t = threadIdx.x;
    __shared__ float rs[256], rq[256];
    float s = g_ps[t * CC + o] + g_ps[(t + 256) * CC + o];
    float q = g_pq[t * CC + o] + g_pq[(t + 256) * CC + o];
    rs[t] = s; rq[t] = q; __syncthreads();
    for (int st = 128; st > 0; st >>= 1){
        if (t < st){ rs[t] += rs[t+st]; rq[t] += rq[t+st]; }
        __syncthreads();
    }
    if (t == 0){
        float inv = 1.0f / (float)(BB * NN);
        float mean = rs[0] * inv;
        float var  = rq[0] * inv - mean * mean;
        float rstd = rsqrtf(var + 1e-5f);
        float sc = gamma[o] * rstd;
        g_scale[o] = sc;
        g_shift[o] = beta[o] - mean * sc;
    }
}
__global__ void k_final(const float* __restrict__ x, float* __restrict__ out){
    size_t i = ((size_t)blockIdx.x * blockDim.x + threadIdx.x) * 4;
    int o = (int)(i & (CC - 1));
    float4 t4 = *(const float4*)(g_t + i);
    float4 x4 = *(const float4*)(x + i);
    float4 sc = *(const float4*)(g_scale + o);
    float4 sh = *(const float4*)(g_shift + o);
    float4 r;
    r.x = x4.x + fmaxf(fmaf(t4.x, sc.x, sh.x), 0.f);
    r.y = x4.y + fmaxf(fmaf(t4.y, sc.y, sh.y), 0.f);
    r.z = x4.z + fmaxf(fmaf(t4.z, sc.z, sh.z), 0.f);
    r.w = x4.w + fmaxf(fmaf(t4.w, sc.w, sh.w), 0.f);
    *(float4*)(out + i) = r;
}

// ---------------- launch ----------------------------------------------------
extern "C" void kernel_launch(void* const* d_in, const int* in_sizes, int n_in,
                              void* d_out, int out_size){
    (void)in_sizes; (void)n_in; (void)out_size;
    const float* x     = (const float*)d_in[1];
    const float* Wq    = (const float*)d_in[2];
    const float* Wv    = (const float*)d_in[3];
    const float* bv    = (const float*)d_in[4];
    const float* Wt    = (const float*)d_in[5];
    const float* bt    = (const float*)d_in[6];
    const float* gamma = (const float*)d_in[7];
    const float* beta  = (const float*)d_in[8];
    float* out = (float*)d_out;

    static bool attr_done = false;
    if (!attr_done){
        cudaFuncSetAttribute(kt1, cudaFuncAttributeMaxDynamicSharedMemorySize, SDYN);
        cudaFuncSetAttribute(kt2, cudaFuncAttributeMaxDynamicSharedMemorySize, SDYN);
        cudaFuncSetAttribute(kt6, cudaFuncAttributeMaxDynamicSharedMemorySize, SDYN);
        attr_done = true;
    }

    k_cvt_x  <<<16384, 256>>>(x);
    k_cvt_w  <<<768,   256>>>(Wq, Wv, Wt);
    kt1      <<<dim3(32, 2, 48), 256, SDYN>>>(bv);
    kt2      <<<dim3(2, 2, BB),  256, SDYN>>>();
    k_softmax<<<BB*CC, 256>>>();
    k_colsum <<<BB,    256>>>();
    k_mgemm  <<<dim3(4, 4, BB), 256>>>(Wt);
    kt6      <<<dim3(32, 2, BB), 256, SDYN>>>(bt);
    k_bnpart <<<512, 256>>>();
    k_bnfin  <<<CC,  256>>>(gamma, beta);
    k_final  <<<16384, 256>>>(x, out);
}

// round 4
// speedup vs baseline: 3.0415x; 1.5593x over previous
#include <cuda_runtime.h>
#include <cuda_bf16.h>
#include <cstdint>

#define BB 16
#define NN 4096
#define CC 256

using bf16 = __nv_bfloat16;

// ---------------- scratch (device globals; no allocation allowed) ----------
__device__ __align__(16) bf16  g_xhi[(size_t)BB*NN*CC];   // x split, [B][N][C]
__device__ __align__(16) bf16  g_xlo[(size_t)BB*NN*CC];
__device__ __align__(16) bf16  g_xThi[(size_t)BB*CC*NN];  // x^T split, [B][C][N]
__device__ __align__(16) bf16  g_xTlo[(size_t)BB*CC*NN];
__device__ __align__(16) bf16  g_vhi[(size_t)BB*NN*CC];   // v^T split, [B][N][C]
__device__ __align__(16) bf16  g_vlo[(size_t)BB*NN*CC];
__device__ __align__(16) bf16  g_Whi[3*CC*CC];            // Wq, Wv, Wt split
__device__ __align__(16) bf16  g_Wlo[3*CC*CC];
__device__ float g_u[(size_t)BB*NN*CC];     // Wt@xc, [B][N][C]
__device__ float g_t[(size_t)BB*NN*CC];     // pre-BN t, [B][N][C]
__device__ float g_Gp[(size_t)4*BB*CC*CC];  // split-K partials of G
__device__ __align__(16) bf16  g_Ghi[(size_t)BB*CC*CC];   // G = x^T x split
__device__ __align__(16) bf16  g_Glo[(size_t)BB*CC*CC];
__device__ __align__(16) bf16  g_E1hi[(size_t)BB*CC*CC];  // E1 = Wq G
__device__ __align__(16) bf16  g_E1lo[(size_t)BB*CC*CC];
__device__ float g_att[(size_t)BB*CC*CC];   // energy -> softmax att (fp32)
__device__ __align__(16) bf16  g_atthi[(size_t)BB*CC*CC]; // att split
__device__ __align__(16) bf16  g_attlo[(size_t)BB*CC*CC];
__device__ __align__(16) bf16  g_Ashi[(size_t)BB*CC*CC];  // Wt/colsum split
__device__ __align__(16) bf16  g_Aslo[(size_t)BB*CC*CC];
__device__ __align__(16) bf16  g_Mhi[(size_t)BB*CC*CC];   // M split [o][c]
__device__ __align__(16) bf16  g_Mlo[(size_t)BB*CC*CC];
__device__ float g_colsum[BB*CC];
__device__ float g_ps[512*CC];
__device__ float g_pq[512*CC];
__device__ float g_scale[CC];
__device__ float g_shift[CC];

#define SDYN 131072   // 2 stages x 64KB

// ---------------- helpers ---------------------------------------------------
__device__ __forceinline__ uint32_t smem_u32(const void* p){
    uint32_t a;
    asm("{ .reg .u64 t; cvta.to.shared.u64 t, %1; cvt.u32.u64 %0, t; }" : "=r"(a) : "l"(p));
    return a;
}
__device__ __forceinline__ uint32_t sw128(uint32_t o){ return o ^ ((o >> 3) & 0x70); }

__device__ __forceinline__ void ldm4(uint32_t* r, uint32_t addr){
    asm volatile("ldmatrix.sync.aligned.m8n8.x4.shared.b16 {%0,%1,%2,%3}, [%4];"
        : "=r"(r[0]), "=r"(r[1]), "=r"(r[2]), "=r"(r[3]) : "r"(addr));
}
__device__ __forceinline__ void mma_bf16(float* c, const uint32_t* a, const uint32_t* b){
    asm volatile("mma.sync.aligned.m16n8k16.row.col.f32.bf16.bf16.f32 "
        "{%0,%1,%2,%3}, {%4,%5,%6,%7}, {%8,%9}, {%0,%1,%2,%3};"
        : "+f"(c[0]), "+f"(c[1]), "+f"(c[2]), "+f"(c[3])
        : "r"(a[0]), "r"(a[1]), "r"(a[2]), "r"(a[3]), "r"(b[0]), "r"(b[1]));
}
__device__ __forceinline__ void cpa16(uint32_t dst, const void* src){
    asm volatile("cp.async.cg.shared.global [%0], [%1], 16;" :: "r"(dst), "l"(src));
}
__device__ __forceinline__ void split_store(bf16* hi, bf16* lo, size_t i, float v){
    bf16 h = __float2bfloat16(v);
    hi[i] = h;
    lo[i] = __float2bfloat16(v - __bfloat162float(h));
}
__device__ __forceinline__ void split_pair(float v0, float v1, uint32_t& hi, uint32_t& lo){
    bf16 h0 = __float2bfloat16(v0), h1 = __float2bfloat16(v1);
    float r0 = v0 - __bfloat162float(h0), r1 = v1 - __bfloat162float(h1);
    __nv_bfloat162 ph; ph.x = h0; ph.y = h1;
    __nv_bfloat162 pl = __floats2bfloat162_rn(r0, r1);
    hi = *(uint32_t*)&ph;
    lo = *(uint32_t*)&pl;
}

// ---------------------------------------------------------------------------
// Split-bf16 128x128 GEMM mainloop, cp.async 2-stage pipelined.
// A: M-rows K-major (ldA), B: N-rows K-major (ldB).
// acc += Ahi*Bhi + Ahi*Blo + Alo*Bhi. 256 thr, warps 4(M) x 2(N).
// Stage layout (64KB): Ahi@0 Alo@16K Bhi@32K Blo@48K; rows 128B, SW128.
// ---------------------------------------------------------------------------
__device__ __forceinline__ void ld_chunk(char* smem, int stage, int tid,
        const bf16* __restrict__ Ahi, const bf16* __restrict__ Alo,
        const bf16* __restrict__ Bhi, const bf16* __restrict__ Blo,
        int ldA, int ldB, int c0){
    uint32_t sbase = smem_u32(smem) + stage * 65536;
    #pragma unroll
    for (int i = 0; i < 4; i++){
        int g = tid + i * 256;
        int row = g >> 3, cg = g & 7;
        uint32_t so = sw128((uint32_t)(row * 128 + cg * 16));
        size_t ga = (size_t)row * ldA + c0 + cg * 8;
        size_t gb = (size_t)row * ldB + c0 + cg * 8;
        cpa16(sbase + so,         Ahi + ga);
        cpa16(sbase + 16384 + so, Alo + ga);
        cpa16(sbase + 32768 + so, Bhi + gb);
        cpa16(sbase + 49152 + so, Blo + gb);
    }
    asm volatile("cp.async.commit_group;" ::: "memory");
}

__device__ __forceinline__ void gemm_main(char* smem,
        const bf16* __restrict__ Ahi, const bf16* __restrict__ Alo, int ldA,
        const bf16* __restrict__ Bhi, const bf16* __restrict__ Blo, int ldB,
        int nChunks, float acc[2][8][4])
{
    int tid = threadIdx.x, lane = tid & 31, wid = tid >> 5;
    int warpM = wid & 3, warpN = wid >> 2;
    uint32_t sb0 = smem_u32(smem);

    ld_chunk(smem, 0, tid, Ahi, Alo, Bhi, Blo, ldA, ldB, 0);

    for (int cc = 0; cc < nChunks; cc++){
        if (cc + 1 < nChunks){
            ld_chunk(smem, (cc + 1) & 1, tid, Ahi, Alo, Bhi, Blo, ldA, ldB, (cc + 1) * 64);
            asm volatile("cp.async.wait_group 1;" ::: "memory");
        } else {
            asm volatile("cp.async.wait_group 0;" ::: "memory");
        }
        __syncthreads();
        uint32_t sb = sb0 + (cc & 1) * 65536;
        #pragma unroll
        for (int ks = 0; ks < 4; ks++){
            uint32_t ahi[2][4], alo[2][4];
            #pragma unroll
            for (int mf = 0; mf < 2; mf++){
                int row = warpM * 32 + mf * 16 + (lane & 15);
                uint32_t off = sw128((uint32_t)(row * 128 + ks * 32 + (lane >> 4) * 16));
                ldm4(ahi[mf], sb + off);
                ldm4(alo[mf], sb + 16384 + off);
            }
            #pragma unroll
            for (int ng = 0; ng < 4; ng++){
                int rowb = warpN * 64 + ng * 16 + (lane & 15);
                uint32_t off = sw128((uint32_t)(rowb * 128 + ks * 32 + (lane >> 4) * 16));
                uint32_t bh[4], bl[4];
                ldm4(bh, sb + 32768 + off);
                ldm4(bl, sb + 49152 + off);
                uint32_t bh0[2] = {bh[0], bh[2]}, bh1[2] = {bh[1], bh[3]};
                uint32_t bl0[2] = {bl[0], bl[2]}, bl1[2] = {bl[1], bl[3]};
                #pragma unroll
                for (int mf = 0; mf < 2; mf++){
                    mma_bf16(acc[mf][ng*2],     ahi[mf], bh0);
                    mma_bf16(acc[mf][ng*2],     ahi[mf], bl0);
                    mma_bf16(acc[mf][ng*2],     alo[mf], bh0);
                    mma_bf16(acc[mf][ng*2 + 1], ahi[mf], bh1);
                    mma_bf16(acc[mf][ng*2 + 1], ahi[mf], bl1);
                    mma_bf16(acc[mf][ng*2 + 1], alo[mf], bh1);
                }
            }
        }
        __syncthreads();
    }
}

// ---------------- conversion: x -> split x AND split x^T --------------------
__global__ void __launch_bounds__(256) k_cvt_x(const float* __restrict__ x){
    int b = blockIdx.z, n0 = blockIdx.x * 64, c0 = blockIdx.y * 64;
    __shared__ float xs[64][65];
    int t = threadIdx.x;
    const float* xb = x + ((size_t)b * NN + n0) * CC + c0;
    #pragma unroll
    for (int p = 0; p < 4; p++){
        int row = p * 16 + (t >> 4);
        int c4  = (t & 15) * 4;
        float4 v = *(const float4*)(xb + (size_t)row * CC + c4);
        uint32_t h0, l0, h1, l1;
        split_pair(v.x, v.y, h0, l0);
        split_pair(v.z, v.w, h1, l1);
        size_t di = ((size_t)b * NN + n0 + row) * CC + c0 + c4;
        *(uint2*)(g_xhi + di) = make_uint2(h0, h1);
        *(uint2*)(g_xlo + di) = make_uint2(l0, l1);
        xs[row][c4 + 0] = v.x; xs[row][c4 + 1] = v.y;
        xs[row][c4 + 2] = v.z; xs[row][c4 + 3] = v.w;
    }
    __syncthreads();
    #pragma unroll
    for (int p = 0; p < 4; p++){
        int cl = p * 16 + (t >> 4);
        int n4 = (t & 15) * 4;
        float v0 = xs[n4][cl], v1 = xs[n4+1][cl], v2 = xs[n4+2][cl], v3 = xs[n4+3][cl];
        uint32_t h0, l0, h1, l1;
        split_pair(v0, v1, h0, l0);
        split_pair(v2, v3, h1, l1);
        size_t di = ((size_t)b * CC + c0 + cl) * NN + n0 + n4;
        *(uint2*)(g_xThi + di) = make_uint2(h0, h1);
        *(uint2*)(g_xTlo + di) = make_uint2(l0, l1);
    }
}
__global__ void k_cvt_w(const float* __restrict__ Wq, const float* __restrict__ Wv,
                        const float* __restrict__ Wt){
    int idx = blockIdx.x * blockDim.x + threadIdx.x;
    int which = idx >> 16, rem = idx & 65535;
    const float* s = (which == 0) ? Wq : (which == 1) ? Wv : Wt;
    split_store(g_Whi, g_Wlo, idx, s[rem]);
}

// ---------------- KT1: v^T / u ---------------------------------------------
// z in [0,32): b = z&15, which = 1 + (z>>4).  A = x rows n, B = W rows o.
__global__ void __launch_bounds__(256)
kt1(const float* __restrict__ bv){
    extern __shared__ char smem[];
    int b = blockIdx.z & 15, which = 1 + (blockIdx.z >> 4);
    size_t xoff = (size_t)b * NN * CC;
    int mBase = blockIdx.x * 128, nBase = blockIdx.y * 128;
    const bf16* Ahi = g_xhi + xoff + (size_t)mBase * CC;
    const bf16* Alo = g_xlo + xoff + (size_t)mBase * CC;
    int w = which * CC * CC;
    const bf16* Bhi = g_Whi + w + nBase * CC;
    const bf16* Blo = g_Wlo + w + nBase * CC;
    float acc[2][8][4] = {};
    gemm_main(smem, Ahi, Alo, CC, Bhi, Blo, CC, 4, acc);

    int tid = threadIdx.x, lane = tid & 31, wid = tid >> 5;
    int warpM = wid & 3, warpN = wid >> 2;
    int gr = lane >> 2, gc = (lane & 3) * 2;
    #pragma unroll
    for (int mf = 0; mf < 2; mf++)
        #pragma unroll
        for (int nf = 0; nf < 8; nf++){
            float* c = acc[mf][nf];
            int row0 = warpM * 32 + mf * 16 + gr;
            int col  = warpN * 64 + nf * 8 + gc;
            #pragma unroll
            for (int h = 0; h < 2; h++){
                int n = mBase + row0 + h * 8, o = nBase + col;
                size_t di = ((size_t)b * NN + n) * CC + o;
                if (which == 1){
                    uint32_t hi, lo;
                    split_pair(c[2*h] + bv[o], c[2*h+1] + bv[o+1], hi, lo);
                    *(uint32_t*)(g_vhi + di) = hi;
                    *(uint32_t*)(g_vlo + di) = lo;
                } else {
                    *(float2*)(g_u + di) = make_float2(c[2*h], c[2*h+1]);
                }
            }
        }
}

// ---------------- KTG: G = x^T x (split-K x4) -------------------------------
// z = b*4 + ks.  A,B = xT rows (K-major n), K window [ks*1024, +1024)
__global__ void __launch_bounds__(256)
ktG(){
    extern __shared__ char smem[];
    int b = blockIdx.z >> 2, ks = blockIdx.z & 3;
    int cBase = blockIdx.y * 128, dBase = blockIdx.x * 128;
    size_t kOff = (size_t)ks * 1024;
    const bf16* Ah = g_xThi + ((size_t)b * CC + cBase) * NN + kOff;
    const bf16* Al = g_xTlo + ((size_t)b * CC + cBase) * NN + kOff;
    const bf16* Bh = g_xThi + ((size_t)b * CC + dBase) * NN + kOff;
    const bf16* Bl = g_xTlo + ((size_t)b * CC + dBase) * NN + kOff;
    float acc[2][8][4] = {};
    gemm_main(smem, Ah, Al, NN, Bh, Bl, NN, 16, acc);

    int tid = threadIdx.x, lane = tid & 31, wid = tid >> 5;
    int warpM = wid & 3, warpN = wid >> 2;
    int gr = lane >> 2, gc = (lane & 3) * 2;
    float* dst = g_Gp + ((size_t)(ks * BB + b)) * CC * CC;
    #pragma unroll
    for (int mf = 0; mf < 2; mf++)
        #pragma unroll
        for (int nf = 0; nf < 8; nf++){
            float* c = acc[mf][nf];
            int row0 = warpM * 32 + mf * 16 + gr;
            int col  = warpN * 64 + nf * 8 + gc;
            #pragma unroll
            for (int h = 0; h < 2; h++)
                *(float2*)(dst + (size_t)(cBase + row0 + h*8) * CC + dBase + col)
                    = make_float2(c[2*h], c[2*h+1]);
        }
}
__global__ void k_gsum(){
    size_t i = ((size_t)blockIdx.x * blockDim.x + threadIdx.x) * 4;
    const size_t S = (size_t)BB * CC * CC;
    float4 a = *(const float4*)(g_Gp + i);
    float4 b = *(const float4*)(g_Gp + S + i);
    float4 c = *(const float4*)(g_Gp + 2*S + i);
    float4 d = *(const float4*)(g_Gp + 3*S + i);
    float v0 = a.x+b.x+c.x+d.x, v1 = a.y+b.y+c.y+d.y;
    float v2 = a.z+b.z+c.z+d.z, v3 = a.w+b.w+c.w+d.w;
    uint32_t h0,l0,h1,l1;
    split_pair(v0,v1,h0,l0); split_pair(v2,v3,h1,l1);
    *(uint2*)(g_Ghi + i) = make_uint2(h0,h1);
    *(uint2*)(g_Glo + i) = make_uint2(l0,l1);
}

// ---------------- small square GEMMs (K=256, grid 2x2x16) -------------------
// mode 0: E1 = Wq . G        -> split E1 [c][d']
// mode 1: E  = E1 . Wq^T     -> fp32 g_att
// mode 2: M  = As . att      -> split M [o][c]
__global__ void __launch_bounds__(256)
ksq(int mode){
    extern __shared__ char smem[];
    int b = blockIdx.z;
    int mBase = blockIdx.y * 128, nBase = blockIdx.x * 128;
    size_t boff = (size_t)b * CC * CC;
    const bf16 *Ah, *Al, *Bh, *Bl;
    if (mode == 0){
        Ah = g_Whi + mBase * CC;        Al = g_Wlo + mBase * CC;
        Bh = g_Ghi + boff + nBase * CC; Bl = g_Glo + boff + nBase * CC;
    } else if (mode == 1){
        Ah = g_E1hi + boff + mBase * CC; Al = g_E1lo + boff + mBase * CC;
        Bh = g_Whi + nBase * CC;         Bl = g_Wlo + nBase * CC;
    } else {
        Ah = g_Ashi + boff + mBase * CC;  Al = g_Aslo + boff + mBase * CC;
        Bh = g_atthi + boff + nBase * CC; Bl = g_attlo + boff + nBase * CC;
    }
    float acc[2][8][4] = {};
    gemm_main(smem, Ah, Al, CC, Bh, Bl, CC, 4, acc);

    int tid = threadIdx.x, lane = tid & 31, wid = tid >> 5;
    int warpM = wid & 3, warpN = wid >> 2;
    int gr = lane >> 2, gc = (lane & 3) * 2;
    #pragma unroll
    for (int mf = 0; mf < 2; mf++)
        #pragma unroll
        for (int nf = 0; nf < 8; nf++){
            float* c = acc[mf][nf];
            int row0 = warpM * 32 + mf * 16 + gr;
            int col  = warpN * 64 + nf * 8 + gc;
            #pragma unroll
            for (int h = 0; h < 2; h++){
                size_t di = boff + (size_t)(mBase + row0 + h*8) * CC + nBase + col;
                if (mode == 1){
                    *(float2*)(g_att + di) = make_float2(c[2*h], c[2*h+1]);
                } else {
                    uint32_t hi, lo;
                    split_pair(c[2*h], c[2*h+1], hi, lo);
                    if (mode == 0){ *(uint32_t*)(g_E1hi + di) = hi; *(uint32_t*)(g_E1lo + di) = lo; }
                    else          { *(uint32_t*)(g_Mhi  + di) = hi; *(uint32_t*)(g_Mlo  + di) = lo; }
                }
            }
        }
}

// ---------------- softmax / colsum / As ------------------------------------
__global__ void k_softmax(){
    size_t row = blockIdx.x;
    float* p = g_att + row * CC;
    int t = threadIdx.x;
    float v = p[t];
    __shared__ float red[256];
    red[t] = v; __syncthreads();
    for (int s = 128; s > 0; s >>= 1){ if (t < s) red[t] = fmaxf(red[t], red[t+s]); __syncthreads(); }
    float mx = red[0]; __syncthreads();
    float e = __expf(v - mx);
    red[t] = e; __syncthreads();
    for (int s = 128; s > 0; s >>= 1){ if (t < s) red[t] += red[t+s]; __syncthreads(); }
    float val = e / red[0];
    p[t] = val;
    split_store(g_atthi, g_attlo, row * CC + t, val);
}
__global__ void k_colsum(){
    int b = blockIdx.x, d = threadIdx.x;
    float s = 0.f;
    for (int c = 0; c < CC; c++) s += g_att[((size_t)b * CC + c) * CC + d];
    g_colsum[b * CC + d] = s;
}
__global__ void k_scaleWt(const float* __restrict__ Wt){
    size_t i = ((size_t)blockIdx.x * blockDim.x + threadIdx.x) * 4;
    int b = (int)(i >> 16);
    int od = (int)(i & 65535);
    int d = od & 255;
    float4 w = *(const float4*)(Wt + od);
    float4 cs = *(const float4*)(g_colsum + b * CC + d);
    float v0 = w.x / (1e-9f + cs.x), v1 = w.y / (1e-9f + cs.y);
    float v2 = w.z / (1e-9f + cs.z), v3 = w.w / (1e-9f + cs.w);
    uint32_t h0,l0,h1,l1;
    split_pair(v0,v1,h0,l0); split_pair(v2,v3,h1,l1);
    *(uint2*)(g_Ashi + i) = make_uint2(h0,h1);
    *(uint2*)(g_Aslo + i) = make_uint2(l0,l1);
}

// ---------------- KT6: t[n,o] = u + bt - vT . M^T --------------------------
__global__ void __launch_bounds__(256)
kt6(const float* __restrict__ bt){
    extern __shared__ char smem[];
    int b = blockIdx.z;
    int mBase = blockIdx.x * 128;   // n
    int oBase = blockIdx.y * 128;   // o
    const bf16* Ah = g_vhi + ((size_t)b * NN + mBase) * CC;
    const bf16* Al = g_vlo + ((size_t)b * NN + mBase) * CC;
    const bf16* Bh = g_Mhi + ((size_t)b * CC + oBase) * CC;
    const bf16* Bl = g_Mlo + ((size_t)b * CC + oBase) * CC;
    float acc[2][8][4] = {};
    gemm_main(smem, Ah, Al, CC, Bh, Bl, CC, 4, acc);

    int tid = threadIdx.x, lane = tid & 31, wid = tid >> 5;
    int warpM = wid & 3, warpN = wid >> 2;
    int gr = lane >> 2, gc = (lane & 3) * 2;
    #pragma unroll
    for (int mf = 0; mf < 2; mf++)
        #pragma unroll
        for (int nf = 0; nf < 8; nf++){
            float* c = acc[mf][nf];
            int row0 = warpM * 32 + mf * 16 + gr;
            int col  = warpN * 64 + nf * 8 + gc;
            #pragma unroll
            for (int h = 0; h < 2; h++){
                int n = mBase + row0 + h * 8, o = oBase + col;
                size_t di = ((size_t)b * NN + n) * CC + o;
                float2 u2 = *(const float2*)(g_u + di);
                *(float2*)(g_t + di) = make_float2(u2.x + bt[o]   - c[2*h],
                                                   u2.y + bt[o+1] - c[2*h+1]);
            }
        }
}

// ---------------- BN stats + final -----------------------------------------
__global__ void k_bnpart(){
    int blk = blockIdx.x, o = threadIdx.x;
    const float* base = g_t + (size_t)blk * 128 * CC + o;
    float s = 0.f, q = 0.f;
    #pragma unroll 4
    for (int r = 0; r < 128; r++){ float v = base[(size_t)r * CC]; s += v; q += v * v; }
    g_ps[blk * CC + o] = s;
    g_pq[blk * CC + o] = q;
}
__global__ void k_bnfin(const float* __restrict__ gamma, const float* __restrict__ beta){
    int o = blockIdx.x, t = threadIdx.x;
    __shared__ float rs[256], rq[256];
    float s = g_ps[t * CC + o] + g_ps[(t + 256) * CC + o];
    float q = g_pq[t * CC + o] + g_pq[(t + 256) * CC + o];
    rs[t] = s; rq[t] = q; __syncthreads();
    for (int st = 128; st > 0; st >>= 1){
        if (t < st){ rs[t] += rs[t+st]; rq[t] += rq[t+st]; }
        __syncthreads();
    }
    if (t == 0){
        float inv = 1.0f / (float)(BB * NN);
        float mean = rs[0] * inv;
        float var  = rq[0] * inv - mean * mean;
        float rstd = rsqrtf(var + 1e-5f);
        float sc = gamma[o] * rstd;
        g_scale[o] = sc;
        g_shift[o] = beta[o] - mean * sc;
    }
}
__global__ void k_final(const float* __restrict__ x, float* __restrict__ out){
    size_t i = ((size_t)blockIdx.x * blockDim.x + threadIdx.x) * 4;
    int o = (int)(i & (CC - 1));
    float4 t4 = *(const float4*)(g_t + i);
    float4 x4 = *(const float4*)(x + i);
    float4 sc = *(const float4*)(g_scale + o);
    float4 sh = *(const float4*)(g_shift + o);
    float4 r;
    r.x = x4.x + fmaxf(fmaf(t4.x, sc.x, sh.x), 0.f);
    r.y = x4.y + fmaxf(fmaf(t4.y, sc.y, sh.y), 0.f);
    r.z = x4.z + fmaxf(fmaf(t4.z, sc.z, sh.z), 0.f);
    r.w = x4.w + fmaxf(fmaf(t4.w, sc.w, sh.w), 0.f);
    *(float4*)(out + i) = r;
}

// ---------------- launch ----------------------------------------------------
extern "C" void kernel_launch(void* const* d_in, const int* in_sizes, int n_in,
                              void* d_out, int out_size){
    (void)in_sizes; (void)n_in; (void)out_size;
    const float* x     = (const float*)d_in[1];
    const float* Wq    = (const float*)d_in[2];
    const float* Wv    = (const float*)d_in[3];
    const float* bv    = (const float*)d_in[4];
    const float* Wt    = (const float*)d_in[5];
    const float* bt    = (const float*)d_in[6];
    const float* gamma = (const float*)d_in[7];
    const float* beta  = (const float*)d_in[8];
    float* out = (float*)d_out;

    static bool attr_done = false;
    if (!attr_done){
        cudaFuncSetAttribute(kt1, cudaFuncAttributeMaxDynamicSharedMemorySize, SDYN);
        cudaFuncSetAttribute(ktG, cudaFuncAttributeMaxDynamicSharedMemorySize, SDYN);
        cudaFuncSetAttribute(ksq, cudaFuncAttributeMaxDynamicSharedMemorySize, SDYN);
        cudaFuncSetAttribute(kt6, cudaFuncAttributeMaxDynamicSharedMemorySize, SDYN);
        attr_done = true;
    }

    k_cvt_x  <<<dim3(64, 4, BB), 256>>>(x);
    k_cvt_w  <<<768, 256>>>(Wq, Wv, Wt);
    kt1      <<<dim3(32, 2, 32), 256, SDYN>>>(bv);
    ktG      <<<dim3(2, 2, 4*BB), 256, SDYN>>>();
    k_gsum   <<<1024, 256>>>();
    ksq      <<<dim3(2, 2, BB), 256, SDYN>>>(0);
    ksq      <<<dim3(2, 2, BB), 256, SDYN>>>(1);
    k_softmax<<<BB*CC, 256>>>();
    k_colsum <<<BB, 256>>>();
    k_scaleWt<<<1024, 256>>>(Wt);
    ksq      <<<dim3(2, 2, BB), 256, SDYN>>>(2);
    kt6      <<<dim3(32, 2, BB), 256, SDYN>>>(bt);
    k_bnpart <<<512, 256>>>();
    k_bnfin  <<<CC, 256>>>(gamma, beta);
    k_final  <<<16384, 256>>>(x, out);
}

// round 5
// speedup vs baseline: 3.7483x; 1.2324x over previous
#include <cuda_runtime.h>
#include <cuda_bf16.h>
#include <cstdint>

#define BB 16
#define NN 4096
#define CC 256

using bf16 = __nv_bfloat16;

// ---------------- scratch (device globals; no allocation allowed) ----------
__device__ __align__(16) bf16  g_xhi[(size_t)BB*NN*CC];   // x split, [B][N][C]
__device__ __align__(16) bf16  g_xlo[(size_t)BB*NN*CC];
__device__ __align__(16) bf16  g_xThi[(size_t)BB*CC*NN];  // x^T split, [B][C][N]
__device__ __align__(16) bf16  g_xTlo[(size_t)BB*CC*NN];
__device__ __align__(16) bf16  g_vhi[(size_t)BB*NN*CC];   // v^T split, [B][N][C]
__device__ __align__(16) bf16  g_vlo[(size_t)BB*NN*CC];
__device__ __align__(16) bf16  g_Whi[3*CC*CC];            // Wq, Wv, Wt split
__device__ __align__(16) bf16  g_Wlo[3*CC*CC];
__device__ float g_u[(size_t)BB*NN*CC];     // Wt@xc, [B][N][C]
__device__ float g_t[(size_t)BB*NN*CC];     // pre-BN t, [B][N][C]
__device__ float g_Gp[(size_t)4*BB*CC*CC];  // split-K partials of G
__device__ __align__(16) bf16  g_Ghi[(size_t)BB*CC*CC];
__device__ __align__(16) bf16  g_Glo[(size_t)BB*CC*CC];
__device__ __align__(16) bf16  g_E1hi[(size_t)BB*CC*CC];
__device__ __align__(16) bf16  g_E1lo[(size_t)BB*CC*CC];
__device__ float g_att[(size_t)BB*CC*CC];
__device__ __align__(16) bf16  g_atthi[(size_t)BB*CC*CC];
__device__ __align__(16) bf16  g_attlo[(size_t)BB*CC*CC];
__device__ __align__(16) bf16  g_Ashi[(size_t)BB*CC*CC];  // Wt/colsum split
__device__ __align__(16) bf16  g_Aslo[(size_t)BB*CC*CC];
__device__ __align__(16) bf16  g_Mhi[(size_t)BB*CC*CC];
__device__ __align__(16) bf16  g_Mlo[(size_t)BB*CC*CC];
__device__ float g_colsum[BB*CC];
__device__ float g_ps[512*CC];
__device__ float g_pq[512*CC];
__device__ float g_scale[CC];
__device__ float g_shift[CC];

// Stage: Ahi(16K) Alo(16K) Bhi(8K) Blo(8K) = 48KB; 2 stages
#define ST_ALO 16384
#define ST_BHI 32768
#define ST_BLO 40960
#define STAGE  49152
#define SDYN   (2*STAGE)

// ---------------- helpers ---------------------------------------------------
__device__ __forceinline__ uint32_t smem_u32(const void* p){
    uint32_t a;
    asm("{ .reg .u64 t; cvta.to.shared.u64 t, %1; cvt.u32.u64 %0, t; }" : "=r"(a) : "l"(p));
    return a;
}
__device__ __forceinline__ uint32_t sw128(uint32_t o){ return o ^ ((o >> 3) & 0x70); }

__device__ __forceinline__ void ldm4(uint32_t* r, uint32_t addr){
    asm volatile("ldmatrix.sync.aligned.m8n8.x4.shared.b16 {%0,%1,%2,%3}, [%4];"
        : "=r"(r[0]), "=r"(r[1]), "=r"(r[2]), "=r"(r[3]) : "r"(addr));
}
__device__ __forceinline__ void mma_bf16(float* c, const uint32_t* a, const uint32_t* b){
    asm volatile("mma.sync.aligned.m16n8k16.row.col.f32.bf16.bf16.f32 "
        "{%0,%1,%2,%3}, {%4,%5,%6,%7}, {%8,%9}, {%0,%1,%2,%3};"
        : "+f"(c[0]), "+f"(c[1]), "+f"(c[2]), "+f"(c[3])
        : "r"(a[0]), "r"(a[1]), "r"(a[2]), "r"(a[3]), "r"(b[0]), "r"(b[1]));
}
__device__ __forceinline__ void cpa16(uint32_t dst, const void* src){
    asm volatile("cp.async.cg.shared.global [%0], [%1], 16;" :: "r"(dst), "l"(src));
}
__device__ __forceinline__ void split_store(bf16* hi, bf16* lo, size_t i, float v){
    bf16 h = __float2bfloat16(v);
    hi[i] = h;
    lo[i] = __float2bfloat16(v - __bfloat162float(h));
}
__device__ __forceinline__ void split_pair(float v0, float v1, uint32_t& hi, uint32_t& lo){
    bf16 h0 = __float2bfloat16(v0), h1 = __float2bfloat16(v1);
    float r0 = v0 - __bfloat162float(h0), r1 = v1 - __bfloat162float(h1);
    __nv_bfloat162 ph; ph.x = h0; ph.y = h1;
    __nv_bfloat162 pl = __floats2bfloat162_rn(r0, r1);
    hi = *(uint32_t*)&ph;
    lo = *(uint32_t*)&pl;
}

// ---------------------------------------------------------------------------
// Split-bf16 128(M)x64(N) GEMM mainloop, cp.async 2-stage, 2 CTAs/SM.
// A: M-rows K-major (ldA), B: N-rows K-major (ldB).
// acc += Ahi*Bhi + Ahi*Blo + Alo*Bhi. 256 thr, warps 4(M) x 2(N), warp 32x32.
// ---------------------------------------------------------------------------
__device__ __forceinline__ void ld_chunk(char* smem, int stage, int tid,
        const bf16* __restrict__ Ahi, const bf16* __restrict__ Alo,
        const bf16* __restrict__ Bhi, const bf16* __restrict__ Blo,
        int ldA, int ldB, int c0){
    uint32_t sbase = smem_u32(smem) + stage * STAGE;
    #pragma unroll
    for (int i = 0; i < 4; i++){           // A: 128 rows x 8 segs
        int g = tid + i * 256;
        int row = g >> 3, cg = g & 7;
        uint32_t so = sw128((uint32_t)(row * 128 + cg * 16));
        size_t ga = (size_t)row * ldA + c0 + cg * 8;
        cpa16(sbase + so,          Ahi + ga);
        cpa16(sbase + ST_ALO + so, Alo + ga);
    }
    #pragma unroll
    for (int i = 0; i < 2; i++){           // B: 64 rows x 8 segs
        int g = tid + i * 256;
        int row = g >> 3, cg = g & 7;
        uint32_t so = sw128((uint32_t)(row * 128 + cg * 16));
        size_t gb = (size_t)row * ldB + c0 + cg * 8;
        cpa16(sbase + ST_BHI + so, Bhi + gb);
        cpa16(sbase + ST_BLO + so, Blo + gb);
    }
    asm volatile("cp.async.commit_group;" ::: "memory");
}

__device__ __forceinline__ void gemm_main(char* smem,
        const bf16* __restrict__ Ahi, const bf16* __restrict__ Alo, int ldA,
        const bf16* __restrict__ Bhi, const bf16* __restrict__ Blo, int ldB,
        int nChunks, float acc[2][4][4])
{
    int tid = threadIdx.x, lane = tid & 31, wid = tid >> 5;
    int warpM = wid & 3, warpN = wid >> 2;
    uint32_t sb0 = smem_u32(smem);

    ld_chunk(smem, 0, tid, Ahi, Alo, Bhi, Blo, ldA, ldB, 0);

    for (int cc = 0; cc < nChunks; cc++){
        if (cc + 1 < nChunks){
            ld_chunk(smem, (cc + 1) & 1, tid, Ahi, Alo, Bhi, Blo, ldA, ldB, (cc + 1) * 64);
            asm volatile("cp.async.wait_group 1;" ::: "memory");
        } else {
            asm volatile("cp.async.wait_group 0;" ::: "memory");
        }
        __syncthreads();
        uint32_t sb = sb0 + (cc & 1) * STAGE;
        #pragma unroll
        for (int ks = 0; ks < 4; ks++){
            uint32_t ahi[2][4], alo[2][4];
            #pragma unroll
            for (int mf = 0; mf < 2; mf++){
                int row = warpM * 32 + mf * 16 + (lane & 15);
                uint32_t off = sw128((uint32_t)(row * 128 + ks * 32 + (lane >> 4) * 16));
                ldm4(ahi[mf], sb + off);
                ldm4(alo[mf], sb + ST_ALO + off);
            }
            #pragma unroll
            for (int ng = 0; ng < 2; ng++){
                int rowb = warpN * 32 + ng * 16 + (lane & 15);
                uint32_t off = sw128((uint32_t)(rowb * 128 + ks * 32 + (lane >> 4) * 16));
                uint32_t bh[4], bl[4];
                ldm4(bh, sb + ST_BHI + off);
                ldm4(bl, sb + ST_BLO + off);
                uint32_t bh0[2] = {bh[0], bh[2]}, bh1[2] = {bh[1], bh[3]};
                uint32_t bl0[2] = {bl[0], bl[2]}, bl1[2] = {bl[1], bl[3]};
                #pragma unroll
                for (int mf = 0; mf < 2; mf++){
                    mma_bf16(acc[mf][ng*2],     ahi[mf], bh0);
                    mma_bf16(acc[mf][ng*2],     ahi[mf], bl0);
                    mma_bf16(acc[mf][ng*2],     alo[mf], bh0);
                    mma_bf16(acc[mf][ng*2 + 1], ahi[mf], bh1);
                    mma_bf16(acc[mf][ng*2 + 1], ahi[mf], bl1);
                    mma_bf16(acc[mf][ng*2 + 1], alo[mf], bh1);
                }
            }
        }
        __syncthreads();
    }
}

// ---------------- conversion: x -> split x AND split x^T --------------------
__global__ void __launch_bounds__(256) k_cvt_x(const float* __restrict__ x){
    int b = blockIdx.z, n0 = blockIdx.x * 64, c0 = blockIdx.y * 64;
    __shared__ float xs[64][65];
    int t = threadIdx.x;
    const float* xb = x + ((size_t)b * NN + n0) * CC + c0;
    #pragma unroll
    for (int p = 0; p < 4; p++){
        int row = p * 16 + (t >> 4);
        int c4  = (t & 15) * 4;
        float4 v = *(const float4*)(xb + (size_t)row * CC + c4);
        uint32_t h0, l0, h1, l1;
        split_pair(v.x, v.y, h0, l0);
        split_pair(v.z, v.w, h1, l1);
        size_t di = ((size_t)b * NN + n0 + row) * CC + c0 + c4;
        *(uint2*)(g_xhi + di) = make_uint2(h0, h1);
        *(uint2*)(g_xlo + di) = make_uint2(l0, l1);
        xs[row][c4 + 0] = v.x; xs[row][c4 + 1] = v.y;
        xs[row][c4 + 2] = v.z; xs[row][c4 + 3] = v.w;
    }
    __syncthreads();
    #pragma unroll
    for (int p = 0; p < 4; p++){
        int cl = p * 16 + (t >> 4);
        int n4 = (t & 15) * 4;
        float v0 = xs[n4][cl], v1 = xs[n4+1][cl], v2 = xs[n4+2][cl], v3 = xs[n4+3][cl];
        uint32_t h0, l0, h1, l1;
        split_pair(v0, v1, h0, l0);
        split_pair(v2, v3, h1, l1);
        size_t di = ((size_t)b * CC + c0 + cl) * NN + n0 + n4;
        *(uint2*)(g_xThi + di) = make_uint2(h0, h1);
        *(uint2*)(g_xTlo + di) = make_uint2(l0, l1);
    }
}
__global__ void k_cvt_w(const float* __restrict__ Wq, const float* __restrict__ Wv,
                        const float* __restrict__ Wt){
    int idx = blockIdx.x * blockDim.x + threadIdx.x;
    int which = idx >> 16, rem = idx & 65535;
    const float* s = (which == 0) ? Wq : (which == 1) ? Wv : Wt;
    split_store(g_Whi, g_Wlo, idx, s[rem]);
}

// ---------------- KT1: v^T / u (M=n 128-tile, N=o 64-tile) ------------------
__global__ void __launch_bounds__(256, 2)
kt1(const float* __restrict__ bv){
    extern __shared__ char smem[];
    int b = blockIdx.z & 15, which = 1 + (blockIdx.z >> 4);
    size_t xoff = (size_t)b * NN * CC;
    int mBase = blockIdx.x * 128, nBase = blockIdx.y * 64;
    const bf16* Ahi = g_xhi + xoff + (size_t)mBase * CC;
    const bf16* Alo = g_xlo + xoff + (size_t)mBase * CC;
    int w = which * CC * CC;
    const bf16* Bhi = g_Whi + w + nBase * CC;
    const bf16* Blo = g_Wlo + w + nBase * CC;
    float acc[2][4][4] = {};
    gemm_main(smem, Ahi, Alo, CC, Bhi, Blo, CC, 4, acc);

    int tid = threadIdx.x, lane = tid & 31, wid = tid >> 5;
    int warpM = wid & 3, warpN = wid >> 2;
    int gr = lane >> 2, gc = (lane & 3) * 2;
    #pragma unroll
    for (int mf = 0; mf < 2; mf++)
        #pragma unroll
        for (int nf = 0; nf < 4; nf++){
            float* c = acc[mf][nf];
            int row0 = warpM * 32 + mf * 16 + gr;
            int col  = warpN * 32 + nf * 8 + gc;
            #pragma unroll
            for (int h = 0; h < 2; h++){
                int n = mBase + row0 + h * 8, o = nBase + col;
                size_t di = ((size_t)b * NN + n) * CC + o;
                if (which == 1){
                    uint32_t hi, lo;
                    split_pair(c[2*h] + bv[o], c[2*h+1] + bv[o+1], hi, lo);
                    *(uint32_t*)(g_vhi + di) = hi;
                    *(uint32_t*)(g_vlo + di) = lo;
                } else {
                    *(float2*)(g_u + di) = make_float2(c[2*h], c[2*h+1]);
                }
            }
        }
}

// ---------------- KTG: G = x^T x (split-K x4) -------------------------------
__global__ void __launch_bounds__(256, 2)
ktG(){
    extern __shared__ char smem[];
    int b = blockIdx.z >> 2, ks = blockIdx.z & 3;
    int cBase = blockIdx.y * 128, dBase = blockIdx.x * 64;
    size_t kOff = (size_t)ks * 1024;
    const bf16* Ah = g_xThi + ((size_t)b * CC + cBase) * NN + kOff;
    const bf16* Al = g_xTlo + ((size_t)b * CC + cBase) * NN + kOff;
    const bf16* Bh = g_xThi + ((size_t)b * CC + dBase) * NN + kOff;
    const bf16* Bl = g_xTlo + ((size_t)b * CC + dBase) * NN + kOff;
    float acc[2][4][4] = {};
    gemm_main(smem, Ah, Al, NN, Bh, Bl, NN, 16, acc);

    int tid = threadIdx.x, lane = tid & 31, wid = tid >> 5;
    int warpM = wid & 3, warpN = wid >> 2;
    int gr = lane >> 2, gc = (lane & 3) * 2;
    float* dst = g_Gp + ((size_t)(ks * BB + b)) * CC * CC;
    #pragma unroll
    for (int mf = 0; mf < 2; mf++)
        #pragma unroll
        for (int nf = 0; nf < 4; nf++){
            float* c = acc[mf][nf];
            int row0 = warpM * 32 + mf * 16 + gr;
            int col  = warpN * 32 + nf * 8 + gc;
            #pragma unroll
            for (int h = 0; h < 2; h++)
                *(float2*)(dst + (size_t)(cBase + row0 + h*8) * CC + dBase + col)
                    = make_float2(c[2*h], c[2*h+1]);
        }
}
__global__ void k_gsum(){
    size_t i = ((size_t)blockIdx.x * blockDim.x + threadIdx.x) * 4;
    const size_t S = (size_t)BB * CC * CC;
    float4 a = *(const float4*)(g_Gp + i);
    float4 b = *(const float4*)(g_Gp + S + i);
    float4 c = *(const float4*)(g_Gp + 2*S + i);
    float4 d = *(const float4*)(g_Gp + 3*S + i);
    float v0 = a.x+b.x+c.x+d.x, v1 = a.y+b.y+c.y+d.y;
    float v2 = a.z+b.z+c.z+d.z, v3 = a.w+b.w+c.w+d.w;
    uint32_t h0,l0,h1,l1;
    split_pair(v0,v1,h0,l0); split_pair(v2,v3,h1,l1);
    *(uint2*)(g_Ghi + i) = make_uint2(h0,h1);
    *(uint2*)(g_Glo + i) = make_uint2(l0,l1);
}

// ---------------- small square GEMMs (K=256) --------------------------------
__global__ void __launch_bounds__(256, 2)
ksq(int mode){
    extern __shared__ char smem[];
    int b = blockIdx.z;
    int mBase = blockIdx.y * 128, nBase = blockIdx.x * 64;
    size_t boff = (size_t)b * CC * CC;
    const bf16 *Ah, *Al, *Bh, *Bl;
    if (mode == 0){
        Ah = g_Whi + mBase * CC;        Al = g_Wlo + mBase * CC;
        Bh = g_Ghi + boff + nBase * CC; Bl = g_Glo + boff + nBase * CC;
    } else if (mode == 1){
        Ah = g_E1hi + boff + mBase * CC; Al = g_E1lo + boff + mBase * CC;
        Bh = g_Whi + nBase * CC;         Bl = g_Wlo + nBase * CC;
    } else {
        Ah = g_Ashi + boff + mBase * CC;  Al = g_Aslo + boff + mBase * CC;
        Bh = g_atthi + boff + nBase * CC; Bl = g_attlo + boff + nBase * CC;
    }
    float acc[2][4][4] = {};
    gemm_main(smem, Ah, Al, CC, Bh, Bl, CC, 4, acc);

    int tid = threadIdx.x, lane = tid & 31, wid = tid >> 5;
    int warpM = wid & 3, warpN = wid >> 2;
    int gr = lane >> 2, gc = (lane & 3) * 2;
    #pragma unroll
    for (int mf = 0; mf < 2; mf++)
        #pragma unroll
        for (int nf = 0; nf < 4; nf++){
            float* c = acc[mf][nf];
            int row0 = warpM * 32 + mf * 16 + gr;
            int col  = warpN * 32 + nf * 8 + gc;
            #pragma unroll
            for (int h = 0; h < 2; h++){
                size_t di = boff + (size_t)(mBase + row0 + h*8) * CC + nBase + col;
                if (mode == 1){
                    *(float2*)(g_att + di) = make_float2(c[2*h], c[2*h+1]);
                } else {
                    uint32_t hi, lo;
                    split_pair(c[2*h], c[2*h+1], hi, lo);
                    if (mode == 0){ *(uint32_t*)(g_E1hi + di) = hi; *(uint32_t*)(g_E1lo + di) = lo; }
                    else          { *(uint32_t*)(g_Mhi  + di) = hi; *(uint32_t*)(g_Mlo  + di) = lo; }
                }
            }
        }
}

// ---------------- softmax / colsum / As ------------------------------------
__global__ void k_softmax(){
    size_t row = blockIdx.x;
    float* p = g_att + row * CC;
    int t = threadIdx.x;
    float v = p[t];
    __shared__ float red[256];
    red[t] = v; __syncthreads();
    for (int s = 128; s > 0; s >>= 1){ if (t < s) red[t] = fmaxf(red[t], red[t+s]); __syncthreads(); }
    float mx = red[0]; __syncthreads();
    float e = __expf(v - mx);
    red[t] = e; __syncthreads();
    for (int s = 128; s > 0; s >>= 1){ if (t < s) red[t] += red[t+s]; __syncthreads(); }
    float val = e / red[0];
    p[t] = val;
    split_store(g_atthi, g_attlo, row * CC + t, val);
}
__global__ void k_colsum(){
    int b = blockIdx.x, d = threadIdx.x;
    float s = 0.f;
    for (int c = 0; c < CC; c++) s += g_att[((size_t)b * CC + c) * CC + d];
    g_colsum[b * CC + d] = s;
}
__global__ void k_scaleWt(const float* __restrict__ Wt){
    size_t i = ((size_t)blockIdx.x * blockDim.x + threadIdx.x) * 4;
    int b = (int)(i >> 16);
    int od = (int)(i & 65535);
    int d = od & 255;
    float4 w = *(const float4*)(Wt + od);
    float4 cs = *(const float4*)(g_colsum + b * CC + d);
    float v0 = w.x / (1e-9f + cs.x), v1 = w.y / (1e-9f + cs.y);
    float v2 = w.z / (1e-9f + cs.z), v3 = w.w / (1e-9f + cs.w);
    uint32_t h0,l0,h1,l1;
    split_pair(v0,v1,h0,l0); split_pair(v2,v3,h1,l1);
    *(uint2*)(g_Ashi + i) = make_uint2(h0,h1);
    *(uint2*)(g_Aslo + i) = make_uint2(l0,l1);
}

// ---------------- KT6: t[n,o] = u + bt - vT . M^T --------------------------
__global__ void __launch_bounds__(256, 2)
kt6(const float* __restrict__ bt){
    extern __shared__ char smem[];
    int b = blockIdx.z;
    int mBase = blockIdx.x * 128;   // n
    int oBase = blockIdx.y * 64;    // o
    const bf16* Ah = g_vhi + ((size_t)b * NN + mBase) * CC;
    const bf16* Al = g_vlo + ((size_t)b * NN + mBase) * CC;
    const bf16* Bh = g_Mhi + ((size_t)b * CC + oBase) * CC;
    const bf16* Bl = g_Mlo + ((size_t)b * CC + oBase) * CC;
    float acc[2][4][4] = {};
    gemm_main(smem, Ah, Al, CC, Bh, Bl, CC, 4, acc);

    int tid = threadIdx.x, lane = tid & 31, wid = tid >> 5;
    int warpM = wid & 3, warpN = wid >> 2;
    int gr = lane >> 2, gc = (lane & 3) * 2;
    #pragma unroll
    for (int mf = 0; mf < 2; mf++)
        #pragma unroll
        for (int nf = 0; nf < 4; nf++){
            float* c = acc[mf][nf];
            int row0 = warpM * 32 + mf * 16 + gr;
            int col  = warpN * 32 + nf * 8 + gc;
            #pragma unroll
            for (int h = 0; h < 2; h++){
                int n = mBase + row0 + h * 8, o = oBase + col;
                size_t di = ((size_t)b * NN + n) * CC + o;
                float2 u2 = *(const float2*)(g_u + di);
                *(float2*)(g_t + di) = make_float2(u2.x + bt[o]   - c[2*h],
                                                   u2.y + bt[o+1] - c[2*h+1]);
            }
        }
}

// ---------------- BN stats + final -----------------------------------------
__global__ void k_bnpart(){
    int blk = blockIdx.x, o = threadIdx.x;
    const float* base = g_t + (size_t)blk * 128 * CC + o;
    float s = 0.f, q = 0.f;
    #pragma unroll 4
    for (int r = 0; r < 128; r++){ float v = base[(size_t)r * CC]; s += v; q += v * v; }
    g_ps[blk * CC + o] = s;
    g_pq[blk * CC + o] = q;
}
__global__ void k_bnfin(const float* __restrict__ gamma, const float* __restrict__ beta){
    int o = blockIdx.x, t = threadIdx.x;
    __shared__ float rs[256], rq[256];
    float s = g_ps[t * CC + o] + g_ps[(t + 256) * CC + o];
    float q = g_pq[t * CC + o] + g_pq[(t + 256) * CC + o];
    rs[t] = s; rq[t] = q; __syncthreads();
    for (int st = 128; st > 0; st >>= 1){
        if (t < st){ rs[t] += rs[t+st]; rq[t] += rq[t+st]; }
        __syncthreads();
    }
    if (t == 0){
        float inv = 1.0f / (float)(BB * NN);
        float mean = rs[0] * inv;
        float var  = rq[0] * inv - mean * mean;
        float rstd = rsqrtf(var + 1e-5f);
        float sc = gamma[o] * rstd;
        g_scale[o] = sc;
        g_shift[o] = beta[o] - mean * sc;
    }
}
__global__ void k_final(const float* __restrict__ x, float* __restrict__ out){
    size_t i = ((size_t)blockIdx.x * blockDim.x + threadIdx.x) * 4;
    int o = (int)(i & (CC - 1));
    float4 t4 = *(const float4*)(g_t + i);
    float4 x4 = *(const float4*)(x + i);
    float4 sc = *(const float4*)(g_scale + o);
    float4 sh = *(const float4*)(g_shift + o);
    float4 r;
    r.x = x4.x + fmaxf(fmaf(t4.x, sc.x, sh.x), 0.f);
    r.y = x4.y + fmaxf(fmaf(t4.y, sc.y, sh.y), 0.f);
    r.z = x4.z + fmaxf(fmaf(t4.z, sc.z, sh.z), 0.f);
    r.w = x4.w + fmaxf(fmaf(t4.w, sc.w, sh.w), 0.f);
    *(float4*)(out + i) = r;
}

// ---------------- launch ----------------------------------------------------
extern "C" void kernel_launch(void* const* d_in, const int* in_sizes, int n_in,
                              void* d_out, int out_size){
    (void)in_sizes; (void)n_in; (void)out_size;
    const float* x     = (const float*)d_in[1];
    const float* Wq    = (const float*)d_in[2];
    const float* Wv    = (const float*)d_in[3];
    const float* bv    = (const float*)d_in[4];
    const float* Wt    = (const float*)d_in[5];
    const float* bt    = (const float*)d_in[6];
    const float* gamma = (const float*)d_in[7];
    const float* beta  = (const float*)d_in[8];
    float* out = (float*)d_out;

    static bool attr_done = false;
    if (!attr_done){
        cudaFuncSetAttribute(kt1, cudaFuncAttributeMaxDynamicSharedMemorySize, SDYN);
        cudaFuncSetAttribute(ktG, cudaFuncAttributeMaxDynamicSharedMemorySize, SDYN);
        cudaFuncSetAttribute(ksq, cudaFuncAttributeMaxDynamicSharedMemorySize, SDYN);
        cudaFuncSetAttribute(kt6, cudaFuncAttributeMaxDynamicSharedMemorySize, SDYN);
        attr_done = true;
    }

    k_cvt_x  <<<dim3(64, 4, BB), 256>>>(x);
    k_cvt_w  <<<768, 256>>>(Wq, Wv, Wt);
    kt1      <<<dim3(32, 4, 32), 256, SDYN>>>(bv);
    ktG      <<<dim3(4, 2, 4*BB), 256, SDYN>>>();
    k_gsum   <<<1024, 256>>>();
    ksq      <<<dim3(4, 2, BB), 256, SDYN>>>(0);
    ksq      <<<dim3(4, 2, BB), 256, SDYN>>>(1);
    k_softmax<<<BB*CC, 256>>>();
    k_colsum <<<BB, 256>>>();
    k_scaleWt<<<1024, 256>>>(Wt);
    ksq      <<<dim3(4, 2, BB), 256, SDYN>>>(2);
    kt6      <<<dim3(32, 4, BB), 256, SDYN>>>(bt);
    k_bnpart <<<512, 256>>>();
    k_bnfin  <<<CC, 256>>>(gamma, beta);
    k_final  <<<16384, 256>>>(x, out);
}

// round 6
// speedup vs baseline: 3.9919x; 1.0650x over previous
#include <cuda_runtime.h>
#include <cuda_bf16.h>
#include <cstdint>

#define BB 16
#define NN 4096
#define CC 256

using bf16 = __nv_bfloat16;

// ---------------- scratch (device globals; no allocation allowed) ----------
__device__ __align__(16) bf16  g_xhi[(size_t)BB*NN*CC];   // x split, [B][N][C]
__device__ __align__(16) bf16  g_xlo[(size_t)BB*NN*CC];
__device__ __align__(16) bf16  g_xThi[(size_t)BB*CC*NN];  // x^T split, [B][C][N]
__device__ __align__(16) bf16  g_xTlo[(size_t)BB*CC*NN];
__device__ __align__(16) bf16  g_vhi[(size_t)BB*NN*CC];   // v^T split, [B][N][C]
__device__ __align__(16) bf16  g_vlo[(size_t)BB*NN*CC];
__device__ __align__(16) bf16  g_Whi[3*CC*CC];            // Wq, Wv, Wt split
__device__ __align__(16) bf16  g_Wlo[3*CC*CC];
__device__ float g_t[(size_t)BB*NN*CC];     // pre-BN t, [B][N][C]
__device__ float g_Gp[(size_t)4*BB*CC*CC];  // split-K partials of G
__device__ __align__(16) bf16  g_Ghi[(size_t)BB*CC*CC];
__device__ __align__(16) bf16  g_Glo[(size_t)BB*CC*CC];
__device__ __align__(16) bf16  g_E1hi[(size_t)BB*CC*CC];
__device__ __align__(16) bf16  g_E1lo[(size_t)BB*CC*CC];
__device__ float g_att[(size_t)BB*CC*CC];
__device__ __align__(16) bf16  g_atthi[(size_t)BB*CC*CC];
__device__ __align__(16) bf16  g_attlo[(size_t)BB*CC*CC];
__device__ __align__(16) bf16  g_Ashi[(size_t)BB*CC*CC];  // Wt/colsum split
__device__ __align__(16) bf16  g_Aslo[(size_t)BB*CC*CC];
__device__ __align__(16) bf16  g_Mhi[(size_t)BB*CC*CC];   // NEGATED M split [o][c]
__device__ __align__(16) bf16  g_Mlo[(size_t)BB*CC*CC];
__device__ float g_colsum[BB*CC];
__device__ float g_ps[512*CC];
__device__ float g_pq[512*CC];
__device__ float g_scale[CC];
__device__ float g_shift[CC];

// Stage: Ahi(16K) Alo(16K) Bhi(8K) Blo(8K) = 48KB; 2 stages
#define ST_ALO 16384
#define ST_BHI 32768
#define ST_BLO 40960
#define STAGE  49152
#define SDYN   (2*STAGE)

// ---------------- helpers ---------------------------------------------------
__device__ __forceinline__ uint32_t smem_u32(const void* p){
    uint32_t a;
    asm("{ .reg .u64 t; cvta.to.shared.u64 t, %1; cvt.u32.u64 %0, t; }" : "=r"(a) : "l"(p));
    return a;
}
__device__ __forceinline__ uint32_t sw128(uint32_t o){ return o ^ ((o >> 3) & 0x70); }

__device__ __forceinline__ void ldm4(uint32_t* r, uint32_t addr){
    asm volatile("ldmatrix.sync.aligned.m8n8.x4.shared.b16 {%0,%1,%2,%3}, [%4];"
        : "=r"(r[0]), "=r"(r[1]), "=r"(r[2]), "=r"(r[3]) : "r"(addr));
}
__device__ __forceinline__ void mma_bf16(float* c, const uint32_t* a, const uint32_t* b){
    asm volatile("mma.sync.aligned.m16n8k16.row.col.f32.bf16.bf16.f32 "
        "{%0,%1,%2,%3}, {%4,%5,%6,%7}, {%8,%9}, {%0,%1,%2,%3};"
        : "+f"(c[0]), "+f"(c[1]), "+f"(c[2]), "+f"(c[3])
        : "r"(a[0]), "r"(a[1]), "r"(a[2]), "r"(a[3]), "r"(b[0]), "r"(b[1]));
}
__device__ __forceinline__ void cpa16(uint32_t dst, const void* src){
    asm volatile("cp.async.cg.shared.global [%0], [%1], 16;" :: "r"(dst), "l"(src));
}
__device__ __forceinline__ void split_store(bf16* hi, bf16* lo, size_t i, float v){
    bf16 h = __float2bfloat16(v);
    hi[i] = h;
    lo[i] = __float2bfloat16(v - __bfloat162float(h));
}
__device__ __forceinline__ void split_pair(float v0, float v1, uint32_t& hi, uint32_t& lo){
    bf16 h0 = __float2bfloat16(v0), h1 = __float2bfloat16(v1);
    float r0 = v0 - __bfloat162float(h0), r1 = v1 - __bfloat162float(h1);
    __nv_bfloat162 ph; ph.x = h0; ph.y = h1;
    __nv_bfloat162 pl = __floats2bfloat162_rn(r0, r1);
    hi = *(uint32_t*)&ph;
    lo = *(uint32_t*)&pl;
}

// ---------------------------------------------------------------------------
// Split-bf16 128(M)x64(N) GEMM building blocks, cp.async 2-stage, 2 CTAs/SM.
// acc += Ahi*Bhi + Ahi*Blo + Alo*Bhi. 256 thr, warps 4(M) x 2(N), warp 32x32.
// ---------------------------------------------------------------------------
__device__ __forceinline__ void ld_chunk(char* smem, int stage, int tid,
        const bf16* __restrict__ Ahi, const bf16* __restrict__ Alo,
        const bf16* __restrict__ Bhi, const bf16* __restrict__ Blo,
        int ldA, int ldB, int c0){
    uint32_t sbase = smem_u32(smem) + stage * STAGE;
    #pragma unroll
    for (int i = 0; i < 4; i++){           // A: 128 rows x 8 segs
        int g = tid + i * 256;
        int row = g >> 3, cg = g & 7;
        uint32_t so = sw128((uint32_t)(row * 128 + cg * 16));
        size_t ga = (size_t)row * ldA + c0 + cg * 8;
        cpa16(sbase + so,          Ahi + ga);
        cpa16(sbase + ST_ALO + so, Alo + ga);
    }
    #pragma unroll
    for (int i = 0; i < 2; i++){           // B: 64 rows x 8 segs
        int g = tid + i * 256;
        int row = g >> 3, cg = g & 7;
        uint32_t so = sw128((uint32_t)(row * 128 + cg * 16));
        size_t gb = (size_t)row * ldB + c0 + cg * 8;
        cpa16(sbase + ST_BHI + so, Bhi + gb);
        cpa16(sbase + ST_BLO + so, Blo + gb);
    }
    asm volatile("cp.async.commit_group;" ::: "memory");
}

__device__ __forceinline__ void compute_chunk(uint32_t sb, int lane,
        int warpM, int warpN, float acc[2][4][4]){
    #pragma unroll
    for (int ks = 0; ks < 4; ks++){
        uint32_t ahi[2][4], alo[2][4];
        #pragma unroll
        for (int mf = 0; mf < 2; mf++){
            int row = warpM * 32 + mf * 16 + (lane & 15);
            uint32_t off = sw128((uint32_t)(row * 128 + ks * 32 + (lane >> 4) * 16));
            ldm4(ahi[mf], sb + off);
            ldm4(alo[mf], sb + ST_ALO + off);
        }
        #pragma unroll
        for (int ng = 0; ng < 2; ng++){
            int rowb = warpN * 32 + ng * 16 + (lane & 15);
            uint32_t off = sw128((uint32_t)(rowb * 128 + ks * 32 + (lane >> 4) * 16));
            uint32_t bh[4], bl[4];
            ldm4(bh, sb + ST_BHI + off);
            ldm4(bl, sb + ST_BLO + off);
            uint32_t bh0[2] = {bh[0], bh[2]}, bh1[2] = {bh[1], bh[3]};
            uint32_t bl0[2] = {bl[0], bl[2]}, bl1[2] = {bl[1], bl[3]};
            #pragma unroll
            for (int mf = 0; mf < 2; mf++){
                mma_bf16(acc[mf][ng*2],     ahi[mf], bh0);
                mma_bf16(acc[mf][ng*2],     ahi[mf], bl0);
                mma_bf16(acc[mf][ng*2],     alo[mf], bh0);
                mma_bf16(acc[mf][ng*2 + 1], ahi[mf], bh1);
                mma_bf16(acc[mf][ng*2 + 1], ahi[mf], bl1);
                mma_bf16(acc[mf][ng*2 + 1], alo[mf], bh1);
            }
        }
    }
}

__device__ __forceinline__ void gemm_main(char* smem,
        const bf16* __restrict__ Ahi, const bf16* __restrict__ Alo, int ldA,
        const bf16* __restrict__ Bhi, const bf16* __restrict__ Blo, int ldB,
        int nChunks, float acc[2][4][4])
{
    int tid = threadIdx.x, lane = tid & 31, wid = tid >> 5;
    int warpM = wid & 3, warpN = wid >> 2;
    uint32_t sb0 = smem_u32(smem);

    ld_chunk(smem, 0, tid, Ahi, Alo, Bhi, Blo, ldA, ldB, 0);
    for (int cc = 0; cc < nChunks; cc++){
        if (cc + 1 < nChunks){
            ld_chunk(smem, (cc + 1) & 1, tid, Ahi, Alo, Bhi, Blo, ldA, ldB, (cc + 1) * 64);
            asm volatile("cp.async.wait_group 1;" ::: "memory");
        } else {
            asm volatile("cp.async.wait_group 0;" ::: "memory");
        }
        __syncthreads();
        compute_chunk(sb0 + (cc & 1) * STAGE, lane, warpM, warpN, acc);
        __syncthreads();
    }
}

// ---------------- conversion: x -> split x AND split x^T --------------------
__global__ void __launch_bounds__(256) k_cvt_x(const float* __restrict__ x){
    int b = blockIdx.z, n0 = blockIdx.x * 64, c0 = blockIdx.y * 64;
    __shared__ float xs[64][65];
    int t = threadIdx.x;
    const float* xb = x + ((size_t)b * NN + n0) * CC + c0;
    #pragma unroll
    for (int p = 0; p < 4; p++){
        int row = p * 16 + (t >> 4);
        int c4  = (t & 15) * 4;
        float4 v = *(const float4*)(xb + (size_t)row * CC + c4);
        uint32_t h0, l0, h1, l1;
        split_pair(v.x, v.y, h0, l0);
        split_pair(v.z, v.w, h1, l1);
        size_t di = ((size_t)b * NN + n0 + row) * CC + c0 + c4;
        *(uint2*)(g_xhi + di) = make_uint2(h0, h1);
        *(uint2*)(g_xlo + di) = make_uint2(l0, l1);
        xs[row][c4 + 0] = v.x; xs[row][c4 + 1] = v.y;
        xs[row][c4 + 2] = v.z; xs[row][c4 + 3] = v.w;
    }
    __syncthreads();
    #pragma unroll
    for (int p = 0; p < 4; p++){
        int cl = p * 16 + (t >> 4);
        int n4 = (t & 15) * 4;
        float v0 = xs[n4][cl], v1 = xs[n4+1][cl], v2 = xs[n4+2][cl], v3 = xs[n4+3][cl];
        uint32_t h0, l0, h1, l1;
        split_pair(v0, v1, h0, l0);
        split_pair(v2, v3, h1, l1);
        size_t di = ((size_t)b * CC + c0 + cl) * NN + n0 + n4;
        *(uint2*)(g_xThi + di) = make_uint2(h0, h1);
        *(uint2*)(g_xTlo + di) = make_uint2(l0, l1);
    }
}
__global__ void k_cvt_w(const float* __restrict__ Wq, const float* __restrict__ Wv,
                        const float* __restrict__ Wt){
    int idx = blockIdx.x * blockDim.x + threadIdx.x;
    int which = idx >> 16, rem = idx & 65535;
    const float* s = (which == 0) ? Wq : (which == 1) ? Wv : Wt;
    split_store(g_Whi, g_Wlo, idx, s[rem]);
}

// ---------------- KT1: v^T only (M=n 128-tile, N=o 64-tile) -----------------
__global__ void __launch_bounds__(256, 2)
kt1(const float* __restrict__ bv){
    extern __shared__ char smem[];
    int b = blockIdx.z;
    size_t xoff = (size_t)b * NN * CC;
    int mBase = blockIdx.x * 128, nBase = blockIdx.y * 64;
    const bf16* Ahi = g_xhi + xoff + (size_t)mBase * CC;
    const bf16* Alo = g_xlo + xoff + (size_t)mBase * CC;
    const bf16* Bhi = g_Whi + CC * CC + nBase * CC;
    const bf16* Blo = g_Wlo + CC * CC + nBase * CC;
    float acc[2][4][4] = {};
    gemm_main(smem, Ahi, Alo, CC, Bhi, Blo, CC, 4, acc);

    int tid = threadIdx.x, lane = tid & 31, wid = tid >> 5;
    int warpM = wid & 3, warpN = wid >> 2;
    int gr = lane >> 2, gc = (lane & 3) * 2;
    #pragma unroll
    for (int mf = 0; mf < 2; mf++)
        #pragma unroll
        for (int nf = 0; nf < 4; nf++){
            float* c = acc[mf][nf];
            int row0 = warpM * 32 + mf * 16 + gr;
            int col  = warpN * 32 + nf * 8 + gc;
            #pragma unroll
            for (int h = 0; h < 2; h++){
                int n = mBase + row0 + h * 8, o = nBase + col;
                size_t di = ((size_t)b * NN + n) * CC + o;
                uint32_t hi, lo;
                split_pair(c[2*h] + bv[o], c[2*h+1] + bv[o+1], hi, lo);
                *(uint32_t*)(g_vhi + di) = hi;
                *(uint32_t*)(g_vlo + di) = lo;
            }
        }
}

// ---------------- KTG: G = x^T x (split-K x4) -------------------------------
__global__ void __launch_bounds__(256, 2)
ktG(){
    extern __shared__ char smem[];
    int b = blockIdx.z >> 2, ks = blockIdx.z & 3;
    int cBase = blockIdx.y * 128, dBase = blockIdx.x * 64;
    size_t kOff = (size_t)ks * 1024;
    const bf16* Ah = g_xThi + ((size_t)b * CC + cBase) * NN + kOff;
    const bf16* Al = g_xTlo + ((size_t)b * CC + cBase) * NN + kOff;
    const bf16* Bh = g_xThi + ((size_t)b * CC + dBase) * NN + kOff;
    const bf16* Bl = g_xTlo + ((size_t)b * CC + dBase) * NN + kOff;
    float acc[2][4][4] = {};
    gemm_main(smem, Ah, Al, NN, Bh, Bl, NN, 16, acc);

    int tid = threadIdx.x, lane = tid & 31, wid = tid >> 5;
    int warpM = wid & 3, warpN = wid >> 2;
    int gr = lane >> 2, gc = (lane & 3) * 2;
    float* dst = g_Gp + ((size_t)(ks * BB + b)) * CC * CC;
    #pragma unroll
    for (int mf = 0; mf < 2; mf++)
        #pragma unroll
        for (int nf = 0; nf < 4; nf++){
            float* c = acc[mf][nf];
            int row0 = warpM * 32 + mf * 16 + gr;
            int col  = warpN * 32 + nf * 8 + gc;
            #pragma unroll
            for (int h = 0; h < 2; h++)
                *(float2*)(dst + (size_t)(cBase + row0 + h*8) * CC + dBase + col)
                    = make_float2(c[2*h], c[2*h+1]);
        }
}
__global__ void k_gsum(){
    size_t i = ((size_t)blockIdx.x * blockDim.x + threadIdx.x) * 4;
    const size_t S = (size_t)BB * CC * CC;
    float4 a = *(const float4*)(g_Gp + i);
    float4 b = *(const float4*)(g_Gp + S + i);
    float4 c = *(const float4*)(g_Gp + 2*S + i);
    float4 d = *(const float4*)(g_Gp + 3*S + i);
    float v0 = a.x+b.x+c.x+d.x, v1 = a.y+b.y+c.y+d.y;
    float v2 = a.z+b.z+c.z+d.z, v3 = a.w+b.w+c.w+d.w;
    uint32_t h0,l0,h1,l1;
    split_pair(v0,v1,h0,l0); split_pair(v2,v3,h1,l1);
    *(uint2*)(g_Ghi + i) = make_uint2(h0,h1);
    *(uint2*)(g_Glo + i) = make_uint2(l0,l1);
}

// ---------------- small square GEMMs (K=256) --------------------------------
// mode 0: E1 = Wq.G ; mode 1: E = E1.Wq^T (fp32) ; mode 2: -M = -(As.att) split
__global__ void __launch_bounds__(256, 2)
ksq(int mode){
    extern __shared__ char smem[];
    int b = blockIdx.z;
    int mBase = blockIdx.y * 128, nBase = blockIdx.x * 64;
    size_t boff = (size_t)b * CC * CC;
    const bf16 *Ah, *Al, *Bh, *Bl;
    if (mode == 0){
        Ah = g_Whi + mBase * CC;        Al = g_Wlo + mBase * CC;
        Bh = g_Ghi + boff + nBase * CC; Bl = g_Glo + boff + nBase * CC;
    } else if (mode == 1){
        Ah = g_E1hi + boff + mBase * CC; Al = g_E1lo + boff + mBase * CC;
        Bh = g_Whi + nBase * CC;         Bl = g_Wlo + nBase * CC;
    } else {
        Ah = g_Ashi + boff + mBase * CC;  Al = g_Aslo + boff + mBase * CC;
        Bh = g_atthi + boff + nBase * CC; Bl = g_attlo + boff + nBase * CC;
    }
    float acc[2][4][4] = {};
    gemm_main(smem, Ah, Al, CC, Bh, Bl, CC, 4, acc);

    int tid = threadIdx.x, lane = tid & 31, wid = tid >> 5;
    int warpM = wid & 3, warpN = wid >> 2;
    int gr = lane >> 2, gc = (lane & 3) * 2;
    #pragma unroll
    for (int mf = 0; mf < 2; mf++)
        #pragma unroll
        for (int nf = 0; nf < 4; nf++){
            float* c = acc[mf][nf];
            int row0 = warpM * 32 + mf * 16 + gr;
            int col  = warpN * 32 + nf * 8 + gc;
            #pragma unroll
            for (int h = 0; h < 2; h++){
                size_t di = boff + (size_t)(mBase + row0 + h*8) * CC + nBase + col;
                if (mode == 1){
                    *(float2*)(g_att + di) = make_float2(c[2*h], c[2*h+1]);
                } else if (mode == 0){
                    uint32_t hi, lo;
                    split_pair(c[2*h], c[2*h+1], hi, lo);
                    *(uint32_t*)(g_E1hi + di) = hi; *(uint32_t*)(g_E1lo + di) = lo;
                } else {
                    uint32_t hi, lo;
                    split_pair(-c[2*h], -c[2*h+1], hi, lo);   // store NEGATED M
                    *(uint32_t*)(g_Mhi + di) = hi; *(uint32_t*)(g_Mlo + di) = lo;
                }
            }
        }
}

// ---------------- softmax / colsum / As ------------------------------------
__global__ void k_softmax(){
    size_t row = blockIdx.x;
    float* p = g_att + row * CC;
    int t = threadIdx.x;
    float v = p[t];
    __shared__ float red[256];
    red[t] = v; __syncthreads();
    for (int s = 128; s > 0; s >>= 1){ if (t < s) red[t] = fmaxf(red[t], red[t+s]); __syncthreads(); }
    float mx = red[0]; __syncthreads();
    float e = __expf(v - mx);
    red[t] = e; __syncthreads();
    for (int s = 128; s > 0; s >>= 1){ if (t < s) red[t] += red[t+s]; __syncthreads(); }
    float val = e / red[0];
    p[t] = val;
    split_store(g_atthi, g_attlo, row * CC + t, val);
}
__global__ void k_colsum(){
    int b = blockIdx.x, d = threadIdx.x;
    float s = 0.f;
    for (int c = 0; c < CC; c++) s += g_att[((size_t)b * CC + c) * CC + d];
    g_colsum[b * CC + d] = s;
}
__global__ void k_scaleWt(const float* __restrict__ Wt){
    size_t i = ((size_t)blockIdx.x * blockDim.x + threadIdx.x) * 4;
    int b = (int)(i >> 16);
    int od = (int)(i & 65535);
    int d = od & 255;
    float4 w = *(const float4*)(Wt + od);
    float4 cs = *(const float4*)(g_colsum + b * CC + d);
    float v0 = w.x / (1e-9f + cs.x), v1 = w.y / (1e-9f + cs.y);
    float v2 = w.z / (1e-9f + cs.z), v3 = w.w / (1e-9f + cs.w);
    uint32_t h0,l0,h1,l1;
    split_pair(v0,v1,h0,l0); split_pair(v2,v3,h1,l1);
    *(uint2*)(g_Ashi + i) = make_uint2(h0,h1);
    *(uint2*)(g_Aslo + i) = make_uint2(l0,l1);
}

// ---------------- KT6: t = [x|v].[Wt|-M]^T + bt  (K=512, 8 chunks) ----------
__global__ void __launch_bounds__(256, 2)
kt6(const float* __restrict__ bt){
    extern __shared__ char smem[];
    int b = blockIdx.z;
    int mBase = blockIdx.x * 128;   // n
    int oBase = blockIdx.y * 64;    // o
    size_t nrow = (size_t)b * NN + mBase;
    size_t boff = (size_t)b * CC * CC;
    const bf16* Ah[2] = { g_xhi + nrow * CC, g_vhi + nrow * CC };
    const bf16* Al[2] = { g_xlo + nrow * CC, g_vlo + nrow * CC };
    const bf16* Bh[2] = { g_Whi + 2*CC*CC + oBase * CC, g_Mhi + boff + oBase * CC };
    const bf16* Bl[2] = { g_Wlo + 2*CC*CC + oBase * CC, g_Mlo + boff + oBase * CC };

    int tid = threadIdx.x, lane = tid & 31, wid = tid >> 5;
    int warpM = wid & 3, warpN = wid >> 2;
    uint32_t sb0 = smem_u32(smem);
    float acc[2][4][4] = {};

    ld_chunk(smem, 0, tid, Ah[0], Al[0], Bh[0], Bl[0], CC, CC, 0);
    for (int cc = 0; cc < 8; cc++){
        if (cc + 1 < 8){
            int s = (cc + 1) >> 2;
            ld_chunk(smem, (cc + 1) & 1, tid, Ah[s], Al[s], Bh[s], Bl[s],
                     CC, CC, ((cc + 1) & 3) * 64);
            asm volatile("cp.async.wait_group 1;" ::: "memory");
        } else {
            asm volatile("cp.async.wait_group 0;" ::: "memory");
        }
        __syncthreads();
        compute_chunk(sb0 + (cc & 1) * STAGE, lane, warpM, warpN, acc);
        __syncthreads();
    }

    int gr = lane >> 2, gc = (lane & 3) * 2;
    #pragma unroll
    for (int mf = 0; mf < 2; mf++)
        #pragma unroll
        for (int nf = 0; nf < 4; nf++){
            float* c = acc[mf][nf];
            int row0 = warpM * 32 + mf * 16 + gr;
            int col  = warpN * 32 + nf * 8 + gc;
            #pragma unroll
            for (int h = 0; h < 2; h++){
                int n = mBase + row0 + h * 8, o = oBase + col;
                size_t di = ((size_t)b * NN + n) * CC + o;
                *(float2*)(g_t + di) = make_float2(c[2*h]   + bt[o],
                                                   c[2*h+1] + bt[o+1]);
            }
        }
}

// ---------------- BN stats + final -----------------------------------------
__global__ void k_bnpart(){
    int blk = blockIdx.x, o = threadIdx.x;
    const float* base = g_t + (size_t)blk * 128 * CC + o;
    float s = 0.f, q = 0.f;
    #pragma unroll 4
    for (int r = 0; r < 128; r++){ float v = base[(size_t)r * CC]; s += v; q += v * v; }
    g_ps[blk * CC + o] = s;
    g_pq[blk * CC + o] = q;
}
__global__ void k_bnfin(const float* __restrict__ gamma, const float* __restrict__ beta){
    int o = blockIdx.x, t = threadIdx.x;
    __shared__ float rs[256], rq[256];
    float s = g_ps[t * CC + o] + g_ps[(t + 256) * CC + o];
    float q = g_pq[t * CC + o] + g_pq[(t + 256) * CC + o];
    rs[t] = s; rq[t] = q; __syncthreads();
    for (int st = 128; st > 0; st >>= 1){
        if (t < st){ rs[t] += rs[t+st]; rq[t] += rq[t+st]; }
        __syncthreads();
    }
    if (t == 0){
        float inv = 1.0f / (float)(BB * NN);
        float mean = rs[0] * inv;
        float var  = rq[0] * inv - mean * mean;
        float rstd = rsqrtf(var + 1e-5f);
        float sc = gamma[o] * rstd;
        g_scale[o] = sc;
        g_shift[o] = beta[o] - mean * sc;
    }
}
__global__ void k_final(const float* __restrict__ x, float* __restrict__ out){
    size_t i = ((size_t)blockIdx.x * blockDim.x + threadIdx.x) * 4;
    int o = (int)(i & (CC - 1));
    float4 t4 = *(const float4*)(g_t + i);
    float4 x4 = *(const float4*)(x + i);
    float4 sc = *(const float4*)(g_scale + o);
    float4 sh = *(const float4*)(g_shift + o);
    float4 r;
    r.x = x4.x + fmaxf(fmaf(t4.x, sc.x, sh.x), 0.f);
    r.y = x4.y + fmaxf(fmaf(t4.y, sc.y, sh.y), 0.f);
    r.z = x4.z + fmaxf(fmaf(t4.z, sc.z, sh.z), 0.f);
    r.w = x4.w + fmaxf(fmaf(t4.w, sc.w, sh.w), 0.f);
    *(float4*)(out + i) = r;
}

// ---------------- launch ----------------------------------------------------
extern "C" void kernel_launch(void* const* d_in, const int* in_sizes, int n_in,
                              void* d_out, int out_size){
    (void)in_sizes; (void)n_in; (void)out_size;
    const float* x     = (const float*)d_in[1];
    const float* Wq    = (const float*)d_in[2];
    const float* Wv    = (const float*)d_in[3];
    const float* bv    = (const float*)d_in[4];
    const float* Wt    = (const float*)d_in[5];
    const float* bt    = (const float*)d_in[6];
    const float* gamma = (const float*)d_in[7];
    const float* beta  = (const float*)d_in[8];
    float* out = (float*)d_out;

    static cudaStream_t s2 = nullptr;
    static cudaEvent_t eFork = nullptr, eJoin = nullptr;
    if (!s2){
        cudaStreamCreateWithFlags(&s2, cudaStreamNonBlocking);
        cudaEventCreateWithFlags(&eFork, cudaEventDisableTiming);
        cudaEventCreateWithFlags(&eJoin, cudaEventDisableTiming);
        cudaFuncSetAttribute(kt1, cudaFuncAttributeMaxDynamicSharedMemorySize, SDYN);
        cudaFuncSetAttribute(ktG, cudaFuncAttributeMaxDynamicSharedMemorySize, SDYN);
        cudaFuncSetAttribute(ksq, cudaFuncAttributeMaxDynamicSharedMemorySize, SDYN);
        cudaFuncSetAttribute(kt6, cudaFuncAttributeMaxDynamicSharedMemorySize, SDYN);
    }

    k_cvt_x  <<<dim3(64, 4, BB), 256>>>(x);
    k_cvt_w  <<<768, 256>>>(Wq, Wv, Wt);

    // fork: v-projection runs concurrently with the attention chain
    cudaEventRecord(eFork, 0);
    cudaStreamWaitEvent(s2, eFork, 0);
    kt1      <<<dim3(32, 4, BB), 256, SDYN, s2>>>(bv);
    cudaEventRecord(eJoin, s2);

    ktG      <<<dim3(4, 2, 4*BB), 256, SDYN>>>();
    k_gsum   <<<1024, 256>>>();
    ksq      <<<dim3(4, 2, BB), 256, SDYN>>>(0);
    ksq      <<<dim3(4, 2, BB), 256, SDYN>>>(1);
    k_softmax<<<BB*CC, 256>>>();
    k_colsum <<<BB, 256>>>();
    k_scaleWt<<<1024, 256>>>(Wt);
    ksq      <<<dim3(4, 2, BB), 256, SDYN>>>(2);

    cudaStreamWaitEvent(0, eJoin, 0);     // join before fused kt6
    kt6      <<<dim3(32, 4, BB), 256, SDYN>>>(bt);
    k_bnpart <<<512, 256>>>();
    k_bnfin  <<<CC, 256>>>(gamma, beta);
    k_final  <<<16384, 256>>>(x, out);
}

// round 7
// speedup vs baseline: 4.2111x; 1.0549x over previous
#include <cuda_runtime.h>
#include <cuda_bf16.h>
#include <cstdint>

#define BB 16
#define NN 4096
#define CC 256

using bf16 = __nv_bfloat16;

// ---------------- scratch (device globals; no allocation allowed) ----------
__device__ __align__(16) bf16  g_xhi[(size_t)BB*NN*CC];   // x split, [B][N][C]
__device__ __align__(16) bf16  g_xlo[(size_t)BB*NN*CC];
__device__ __align__(16) bf16  g_xThi[(size_t)BB*CC*NN];  // x^T split, [B][C][N]
__device__ __align__(16) bf16  g_xTlo[(size_t)BB*CC*NN];
__device__ __align__(16) bf16  g_vhi[(size_t)BB*NN*CC];   // v^T split, [B][N][C]
__device__ __align__(16) bf16  g_vlo[(size_t)BB*NN*CC];
__device__ __align__(16) bf16  g_Whi[3*CC*CC];            // Wq, Wv, Wt split
__device__ __align__(16) bf16  g_Wlo[3*CC*CC];
__device__ float g_t[(size_t)BB*NN*CC];     // pre-BN t, [B][N][C]
__device__ float g_Gp[(size_t)4*BB*CC*CC];  // split-K partials of G
__device__ __align__(16) bf16  g_Ghi[(size_t)BB*CC*CC];
__device__ __align__(16) bf16  g_Glo[(size_t)BB*CC*CC];
__device__ __align__(16) bf16  g_E1hi[(size_t)BB*CC*CC];
__device__ __align__(16) bf16  g_E1lo[(size_t)BB*CC*CC];
__device__ float g_att[(size_t)BB*CC*CC];
__device__ __align__(16) bf16  g_atthi[(size_t)BB*CC*CC];
__device__ __align__(16) bf16  g_attlo[(size_t)BB*CC*CC];
__device__ __align__(16) bf16  g_Ashi[(size_t)BB*CC*CC];  // Wt/colsum split
__device__ __align__(16) bf16  g_Aslo[(size_t)BB*CC*CC];
__device__ __align__(16) bf16  g_Mhi[(size_t)BB*CC*CC];   // NEGATED M split [o][c]
__device__ __align__(16) bf16  g_Mlo[(size_t)BB*CC*CC];
__device__ float g_colsum[BB*CC];
__device__ float g_bns[CC];                 // fused BN Σt per channel
__device__ float g_bnq[CC];                 // fused BN Σt² per channel
__device__ float g_scale[CC];
__device__ float g_shift[CC];

// Stage: Ahi(16K) Alo(16K) Bhi(8K) Blo(8K) = 48KB; 2 stages
#define ST_ALO 16384
#define ST_BHI 32768
#define ST_BLO 40960
#define STAGE  49152
#define SDYN   (2*STAGE)

// ---------------- helpers ---------------------------------------------------
__device__ __forceinline__ uint32_t smem_u32(const void* p){
    uint32_t a;
    asm("{ .reg .u64 t; cvta.to.shared.u64 t, %1; cvt.u32.u64 %0, t; }" : "=r"(a) : "l"(p));
    return a;
}
__device__ __forceinline__ uint32_t sw128(uint32_t o){ return o ^ ((o >> 3) & 0x70); }

__device__ __forceinline__ void ldm4(uint32_t* r, uint32_t addr){
    asm volatile("ldmatrix.sync.aligned.m8n8.x4.shared.b16 {%0,%1,%2,%3}, [%4];"
        : "=r"(r[0]), "=r"(r[1]), "=r"(r[2]), "=r"(r[3]) : "r"(addr));
}
__device__ __forceinline__ void mma_bf16(float* c, const uint32_t* a, const uint32_t* b){
    asm volatile("mma.sync.aligned.m16n8k16.row.col.f32.bf16.bf16.f32 "
        "{%0,%1,%2,%3}, {%4,%5,%6,%7}, {%8,%9}, {%0,%1,%2,%3};"
        : "+f"(c[0]), "+f"(c[1]), "+f"(c[2]), "+f"(c[3])
        : "r"(a[0]), "r"(a[1]), "r"(a[2]), "r"(a[3]), "r"(b[0]), "r"(b[1]));
}
__device__ __forceinline__ void cpa16(uint32_t dst, const void* src){
    asm volatile("cp.async.cg.shared.global [%0], [%1], 16;" :: "r"(dst), "l"(src));
}
__device__ __forceinline__ void split_store(bf16* hi, bf16* lo, size_t i, float v){
    bf16 h = __float2bfloat16(v);
    hi[i] = h;
    lo[i] = __float2bfloat16(v - __bfloat162float(h));
}
__device__ __forceinline__ void split_pair(float v0, float v1, uint32_t& hi, uint32_t& lo){
    bf16 h0 = __float2bfloat16(v0), h1 = __float2bfloat16(v1);
    float r0 = v0 - __bfloat162float(h0), r1 = v1 - __bfloat162float(h1);
    __nv_bfloat162 ph; ph.x = h0; ph.y = h1;
    __nv_bfloat162 pl = __floats2bfloat162_rn(r0, r1);
    hi = *(uint32_t*)&ph;
    lo = *(uint32_t*)&pl;
}

// ---------------------------------------------------------------------------
// Split-bf16 128(M)x64(N) GEMM building blocks, cp.async 2-stage, 2 CTAs/SM.
// ---------------------------------------------------------------------------
__device__ __forceinline__ void ld_chunk(char* smem, int stage, int tid,
        const bf16* __restrict__ Ahi, const bf16* __restrict__ Alo,
        const bf16* __restrict__ Bhi, const bf16* __restrict__ Blo,
        int ldA, int ldB, int c0){
    uint32_t sbase = smem_u32(smem) + stage * STAGE;
    #pragma unroll
    for (int i = 0; i < 4; i++){           // A: 128 rows x 8 segs
        int g = tid + i * 256;
        int row = g >> 3, cg = g & 7;
        uint32_t so = sw128((uint32_t)(row * 128 + cg * 16));
        size_t ga = (size_t)row * ldA + c0 + cg * 8;
        cpa16(sbase + so,          Ahi + ga);
        cpa16(sbase + ST_ALO + so, Alo + ga);
    }
    #pragma unroll
    for (int i = 0; i < 2; i++){           // B: 64 rows x 8 segs
        int g = tid + i * 256;
        int row = g >> 3, cg = g & 7;
        uint32_t so = sw128((uint32_t)(row * 128 + cg * 16));
        size_t gb = (size_t)row * ldB + c0 + cg * 8;
        cpa16(sbase + ST_BHI + so, Bhi + gb);
        cpa16(sbase + ST_BLO + so, Blo + gb);
    }
    asm volatile("cp.async.commit_group;" ::: "memory");
}

__device__ __forceinline__ void compute_chunk(uint32_t sb, int lane,
        int warpM, int warpN, float acc[2][4][4]){
    #pragma unroll
    for (int ks = 0; ks < 4; ks++){
        uint32_t ahi[2][4], alo[2][4];
        #pragma unroll
        for (int mf = 0; mf < 2; mf++){
            int row = warpM * 32 + mf * 16 + (lane & 15);
            uint32_t off = sw128((uint32_t)(row * 128 + ks * 32 + (lane >> 4) * 16));
            ldm4(ahi[mf], sb + off);
            ldm4(alo[mf], sb + ST_ALO + off);
        }
        #pragma unroll
        for (int ng = 0; ng < 2; ng++){
            int rowb = warpN * 32 + ng * 16 + (lane & 15);
            uint32_t off = sw128((uint32_t)(rowb * 128 + ks * 32 + (lane >> 4) * 16));
            uint32_t bh[4], bl[4];
            ldm4(bh, sb + ST_BHI + off);
            ldm4(bl, sb + ST_BLO + off);
            uint32_t bh0[2] = {bh[0], bh[2]}, bh1[2] = {bh[1], bh[3]};
            uint32_t bl0[2] = {bl[0], bl[2]}, bl1[2] = {bl[1], bl[3]};
            #pragma unroll
            for (int mf = 0; mf < 2; mf++){
                mma_bf16(acc[mf][ng*2],     ahi[mf], bh0);
                mma_bf16(acc[mf][ng*2],     ahi[mf], bl0);
                mma_bf16(acc[mf][ng*2],     alo[mf], bh0);
                mma_bf16(acc[mf][ng*2 + 1], ahi[mf], bh1);
                mma_bf16(acc[mf][ng*2 + 1], ahi[mf], bl1);
                mma_bf16(acc[mf][ng*2 + 1], alo[mf], bh1);
            }
        }
    }
}

__device__ __forceinline__ void gemm_main(char* smem,
        const bf16* __restrict__ Ahi, const bf16* __restrict__ Alo, int ldA,
        const bf16* __restrict__ Bhi, const bf16* __restrict__ Blo, int ldB,
        int nChunks, float acc[2][4][4])
{
    int tid = threadIdx.x, lane = tid & 31, wid = tid >> 5;
    int warpM = wid & 3, warpN = wid >> 2;
    uint32_t sb0 = smem_u32(smem);

    ld_chunk(smem, 0, tid, Ahi, Alo, Bhi, Blo, ldA, ldB, 0);
    for (int cc = 0; cc < nChunks; cc++){
        if (cc + 1 < nChunks){
            ld_chunk(smem, (cc + 1) & 1, tid, Ahi, Alo, Bhi, Blo, ldA, ldB, (cc + 1) * 64);
            asm volatile("cp.async.wait_group 1;" ::: "memory");
        } else {
            asm volatile("cp.async.wait_group 0;" ::: "memory");
        }
        __syncthreads();
        compute_chunk(sb0 + (cc & 1) * STAGE, lane, warpM, warpN, acc);
        __syncthreads();
    }
}

// ---------------- conversion: x -> split x AND split x^T --------------------
__global__ void __launch_bounds__(256) k_cvt_x(const float* __restrict__ x){
    int b = blockIdx.z, n0 = blockIdx.x * 64, c0 = blockIdx.y * 64;
    __shared__ float xs[64][65];
    int t = threadIdx.x;
    const float* xb = x + ((size_t)b * NN + n0) * CC + c0;
    #pragma unroll
    for (int p = 0; p < 4; p++){
        int row = p * 16 + (t >> 4);
        int c4  = (t & 15) * 4;
        float4 v = *(const float4*)(xb + (size_t)row * CC + c4);
        uint32_t h0, l0, h1, l1;
        split_pair(v.x, v.y, h0, l0);
        split_pair(v.z, v.w, h1, l1);
        size_t di = ((size_t)b * NN + n0 + row) * CC + c0 + c4;
        *(uint2*)(g_xhi + di) = make_uint2(h0, h1);
        *(uint2*)(g_xlo + di) = make_uint2(l0, l1);
        xs[row][c4 + 0] = v.x; xs[row][c4 + 1] = v.y;
        xs[row][c4 + 2] = v.z; xs[row][c4 + 3] = v.w;
    }
    __syncthreads();
    #pragma unroll
    for (int p = 0; p < 4; p++){
        int cl = p * 16 + (t >> 4);
        int n4 = (t & 15) * 4;
        float v0 = xs[n4][cl], v1 = xs[n4+1][cl], v2 = xs[n4+2][cl], v3 = xs[n4+3][cl];
        uint32_t h0, l0, h1, l1;
        split_pair(v0, v1, h0, l0);
        split_pair(v2, v3, h1, l1);
        size_t di = ((size_t)b * CC + c0 + cl) * NN + n0 + n4;
        *(uint2*)(g_xThi + di) = make_uint2(h0, h1);
        *(uint2*)(g_xTlo + di) = make_uint2(l0, l1);
    }
}
__global__ void k_cvt_w(const float* __restrict__ Wq, const float* __restrict__ Wv,
                        const float* __restrict__ Wt){
    int idx = blockIdx.x * blockDim.x + threadIdx.x;
    int which = idx >> 16, rem = idx & 65535;
    const float* s = (which == 0) ? Wq : (which == 1) ? Wv : Wt;
    split_store(g_Whi, g_Wlo, idx, s[rem]);
}

// ---------------- KT1: v^T only (M=n 128-tile, N=o 64-tile) -----------------
__global__ void __launch_bounds__(256, 2)
kt1(const float* __restrict__ bv){
    extern __shared__ char smem[];
    int b = blockIdx.z;
    size_t xoff = (size_t)b * NN * CC;
    int mBase = blockIdx.x * 128, nBase = blockIdx.y * 64;
    const bf16* Ahi = g_xhi + xoff + (size_t)mBase * CC;
    const bf16* Alo = g_xlo + xoff + (size_t)mBase * CC;
    const bf16* Bhi = g_Whi + CC * CC + nBase * CC;
    const bf16* Blo = g_Wlo + CC * CC + nBase * CC;
    float acc[2][4][4] = {};
    gemm_main(smem, Ahi, Alo, CC, Bhi, Blo, CC, 4, acc);

    int tid = threadIdx.x, lane = tid & 31, wid = tid >> 5;
    int warpM = wid & 3, warpN = wid >> 2;
    int gr = lane >> 2, gc = (lane & 3) * 2;
    #pragma unroll
    for (int mf = 0; mf < 2; mf++)
        #pragma unroll
        for (int nf = 0; nf < 4; nf++){
            float* c = acc[mf][nf];
            int row0 = warpM * 32 + mf * 16 + gr;
            int col  = warpN * 32 + nf * 8 + gc;
            #pragma unroll
            for (int h = 0; h < 2; h++){
                int n = mBase + row0 + h * 8, o = nBase + col;
                size_t di = ((size_t)b * NN + n) * CC + o;
                uint32_t hi, lo;
                split_pair(c[2*h] + bv[o], c[2*h+1] + bv[o+1], hi, lo);
                *(uint32_t*)(g_vhi + di) = hi;
                *(uint32_t*)(g_vlo + di) = lo;
            }
        }
}

// ---------------- KTG: G = x^T x (split-K x4, symmetric: 6 of 8 tiles) ------
__constant__ int c_tileC[6] = {0, 0, 0, 0, 128, 128};
__constant__ int c_tileD[6] = {0, 64, 128, 192, 128, 192};
__global__ void __launch_bounds__(256, 2)
ktG(){
    extern __shared__ char smem[];
    int b = blockIdx.z >> 2, ks = blockIdx.z & 3;
    int cBase = c_tileC[blockIdx.x], dBase = c_tileD[blockIdx.x];
    size_t kOff = (size_t)ks * 1024;
    const bf16* Ah = g_xThi + ((size_t)b * CC + cBase) * NN + kOff;
    const bf16* Al = g_xTlo + ((size_t)b * CC + cBase) * NN + kOff;
    const bf16* Bh = g_xThi + ((size_t)b * CC + dBase) * NN + kOff;
    const bf16* Bl = g_xTlo + ((size_t)b * CC + dBase) * NN + kOff;
    float acc[2][4][4] = {};
    gemm_main(smem, Ah, Al, NN, Bh, Bl, NN, 16, acc);

    int tid = threadIdx.x, lane = tid & 31, wid = tid >> 5;
    int warpM = wid & 3, warpN = wid >> 2;
    int gr = lane >> 2, gc = (lane & 3) * 2;
    float* dst = g_Gp + ((size_t)(ks * BB + b)) * CC * CC;
    #pragma unroll
    for (int mf = 0; mf < 2; mf++)
        #pragma unroll
        for (int nf = 0; nf < 4; nf++){
            float* c = acc[mf][nf];
            int row0 = warpM * 32 + mf * 16 + gr;
            int col  = warpN * 32 + nf * 8 + gc;
            #pragma unroll
            for (int h = 0; h < 2; h++)
                *(float2*)(dst + (size_t)(cBase + row0 + h*8) * CC + dBase + col)
                    = make_float2(c[2*h], c[2*h+1]);
        }
}
// sum split-K partials; mirror the uncomputed lower-left quadrant (r>=128,c<128)
__global__ void k_gsum(){
    size_t i = ((size_t)blockIdx.x * blockDim.x + threadIdx.x) * 4;
    const size_t S = (size_t)BB * CC * CC;
    int b  = (int)(i >> 16);
    int rc = (int)(i & 65535);
    int r = rc >> 8, c0 = rc & 255;
    float v[4];
    if (r >= 128 && c0 < 128){
        #pragma unroll
        for (int j = 0; j < 4; j++){
            size_t src = (size_t)b * CC * CC + (size_t)(c0 + j) * CC + r;  // transposed
            v[j] = g_Gp[src] + g_Gp[S + src] + g_Gp[2*S + src] + g_Gp[3*S + src];
        }
    } else {
        float4 a = *(const float4*)(g_Gp + i);
        float4 bb = *(const float4*)(g_Gp + S + i);
        float4 cc = *(const float4*)(g_Gp + 2*S + i);
        float4 d = *(const float4*)(g_Gp + 3*S + i);
        v[0] = a.x+bb.x+cc.x+d.x; v[1] = a.y+bb.y+cc.y+d.y;
        v[2] = a.z+bb.z+cc.z+d.z; v[3] = a.w+bb.w+cc.w+d.w;
    }
    uint32_t h0,l0,h1,l1;
    split_pair(v[0],v[1],h0,l0); split_pair(v[2],v[3],h1,l1);
    *(uint2*)(g_Ghi + i) = make_uint2(h0,h1);
    *(uint2*)(g_Glo + i) = make_uint2(l0,l1);
}

// ---------------- small square GEMMs (K=256) --------------------------------
// mode 0: E1 = Wq.G ; mode 1: E = E1.Wq^T (fp32) ; mode 2: -M = -(As.att) split
__global__ void __launch_bounds__(256, 2)
ksq(int mode){
    extern __shared__ char smem[];
    int b = blockIdx.z;
    int mBase = blockIdx.y * 128, nBase = blockIdx.x * 64;
    size_t boff = (size_t)b * CC * CC;
    const bf16 *Ah, *Al, *Bh, *Bl;
    if (mode == 0){
        Ah = g_Whi + mBase * CC;        Al = g_Wlo + mBase * CC;
        Bh = g_Ghi + boff + nBase * CC; Bl = g_Glo + boff + nBase * CC;
    } else if (mode == 1){
        Ah = g_E1hi + boff + mBase * CC; Al = g_E1lo + boff + mBase * CC;
        Bh = g_Whi + nBase * CC;         Bl = g_Wlo + nBase * CC;
    } else {
        Ah = g_Ashi + boff + mBase * CC;  Al = g_Aslo + boff + mBase * CC;
        Bh = g_atthi + boff + nBase * CC; Bl = g_attlo + boff + nBase * CC;
    }
    float acc[2][4][4] = {};
    gemm_main(smem, Ah, Al, CC, Bh, Bl, CC, 4, acc);

    int tid = threadIdx.x, lane = tid & 31, wid = tid >> 5;
    int warpM = wid & 3, warpN = wid >> 2;
    int gr = lane >> 2, gc = (lane & 3) * 2;
    #pragma unroll
    for (int mf = 0; mf < 2; mf++)
        #pragma unroll
        for (int nf = 0; nf < 4; nf++){
            float* c = acc[mf][nf];
            int row0 = warpM * 32 + mf * 16 + gr;
            int col  = warpN * 32 + nf * 8 + gc;
            #pragma unroll
            for (int h = 0; h < 2; h++){
                size_t di = boff + (size_t)(mBase + row0 + h*8) * CC + nBase + col;
                if (mode == 1){
                    *(float2*)(g_att + di) = make_float2(c[2*h], c[2*h+1]);
                } else if (mode == 0){
                    uint32_t hi, lo;
                    split_pair(c[2*h], c[2*h+1], hi, lo);
                    *(uint32_t*)(g_E1hi + di) = hi; *(uint32_t*)(g_E1lo + di) = lo;
                } else {
                    uint32_t hi, lo;
                    split_pair(-c[2*h], -c[2*h+1], hi, lo);   // store NEGATED M
                    *(uint32_t*)(g_Mhi + di) = hi; *(uint32_t*)(g_Mlo + di) = lo;
                }
            }
        }
}

// ---------------- softmax / colsum / As ------------------------------------
__global__ void k_softmax(){
    size_t row = blockIdx.x;
    float* p = g_att + row * CC;
    int t = threadIdx.x;
    float v = p[t];
    __shared__ float red[256];
    red[t] = v; __syncthreads();
    for (int s = 128; s > 0; s >>= 1){ if (t < s) red[t] = fmaxf(red[t], red[t+s]); __syncthreads(); }
    float mx = red[0]; __syncthreads();
    float e = __expf(v - mx);
    red[t] = e; __syncthreads();
    for (int s = 128; s > 0; s >>= 1){ if (t < s) red[t] += red[t+s]; __syncthreads(); }
    float val = e / red[0];
    p[t] = val;
    split_store(g_atthi, g_attlo, row * CC + t, val);
}
__global__ void k_colsum(){
    int b = blockIdx.x, d = threadIdx.x;
    float s = 0.f;
    for (int c = 0; c < CC; c++) s += g_att[((size_t)b * CC + c) * CC + d];
    g_colsum[b * CC + d] = s;
}
__global__ void k_scaleWt(const float* __restrict__ Wt){
    // side duty: zero the fused-BN accumulators (always precedes kt6)
    if (blockIdx.x == 0){ g_bns[threadIdx.x] = 0.f; g_bnq[threadIdx.x] = 0.f; }
    size_t i = ((size_t)blockIdx.x * blockDim.x + threadIdx.x) * 4;
    int b = (int)(i >> 16);
    int od = (int)(i & 65535);
    int d = od & 255;
    float4 w = *(const float4*)(Wt + od);
    float4 cs = *(const float4*)(g_colsum + b * CC + d);
    float v0 = w.x / (1e-9f + cs.x), v1 = w.y / (1e-9f + cs.y);
    float v2 = w.z / (1e-9f + cs.z), v3 = w.w / (1e-9f + cs.w);
    uint32_t h0,l0,h1,l1;
    split_pair(v0,v1,h0,l0); split_pair(v2,v3,h1,l1);
    *(uint2*)(g_Ashi + i) = make_uint2(h0,h1);
    *(uint2*)(g_Aslo + i) = make_uint2(l0,l1);
}

// ---------------- KT6: t = [x|v].[Wt|-M]^T + bt  (K=512) + fused BN sums ----
__global__ void __launch_bounds__(256, 2)
kt6(const float* __restrict__ bt){
    extern __shared__ char smem[];
    int b = blockIdx.z;
    int mBase = blockIdx.x * 128;   // n
    int oBase = blockIdx.y * 64;    // o
    size_t nrow = (size_t)b * NN + mBase;
    size_t boff = (size_t)b * CC * CC;
    const bf16* Ah[2] = { g_xhi + nrow * CC, g_vhi + nrow * CC };
    const bf16* Al[2] = { g_xlo + nrow * CC, g_vlo + nrow * CC };
    const bf16* Bh[2] = { g_Whi + 2*CC*CC + oBase * CC, g_Mhi + boff + oBase * CC };
    const bf16* Bl[2] = { g_Wlo + 2*CC*CC + oBase * CC, g_Mlo + boff + oBase * CC };

    int tid = threadIdx.x, lane = tid & 31, wid = tid >> 5;
    int warpM = wid & 3, warpN = wid >> 2;
    uint32_t sb0 = smem_u32(smem);
    float acc[2][4][4] = {};

    ld_chunk(smem, 0, tid, Ah[0], Al[0], Bh[0], Bl[0], CC, CC, 0);
    for (int cc = 0; cc < 8; cc++){
        if (cc + 1 < 8){
            int s = (cc + 1) >> 2;
            ld_chunk(smem, (cc + 1) & 1, tid, Ah[s], Al[s], Bh[s], Bl[s],
                     CC, CC, ((cc + 1) & 3) * 64);
            asm volatile("cp.async.wait_group 1;" ::: "memory");
        } else {
            asm volatile("cp.async.wait_group 0;" ::: "memory");
        }
        __syncthreads();
        compute_chunk(sb0 + (cc & 1) * STAGE, lane, warpM, warpN, acc);
        __syncthreads();
    }

    __shared__ float bn_s[64], bn_q[64];
    if (tid < 64){ bn_s[tid] = 0.f; bn_q[tid] = 0.f; }
    __syncthreads();

    int gr = lane >> 2, gc = (lane & 3) * 2;
    float sA[4][2], qA[4][2];
    #pragma unroll
    for (int nf = 0; nf < 4; nf++){
        sA[nf][0] = sA[nf][1] = qA[nf][0] = qA[nf][1] = 0.f;
        int col = warpN * 32 + nf * 8 + gc;
        int o = oBase + col;
        float b0 = bt[o], b1 = bt[o + 1];
        #pragma unroll
        for (int mf = 0; mf < 2; mf++){
            float* c = acc[mf][nf];
            int row0 = warpM * 32 + mf * 16 + gr;
            #pragma unroll
            for (int h = 0; h < 2; h++){
                int n = mBase + row0 + h * 8;
                float v0 = c[2*h] + b0, v1 = c[2*h+1] + b1;
                *(float2*)(g_t + ((size_t)b * NN + n) * CC + o) = make_float2(v0, v1);
                sA[nf][0] += v0;       sA[nf][1] += v1;
                qA[nf][0] += v0 * v0;  qA[nf][1] += v1 * v1;
            }
        }
    }
    // reduce over lanes with the same (lane&3): strides 4, 8, 16
    #pragma unroll
    for (int nf = 0; nf < 4; nf++){
        #pragma unroll
        for (int st = 4; st < 32; st <<= 1){
            sA[nf][0] += __shfl_down_sync(0xffffffffu, sA[nf][0], st);
            sA[nf][1] += __shfl_down_sync(0xffffffffu, sA[nf][1], st);
            qA[nf][0] += __shfl_down_sync(0xffffffffu, qA[nf][0], st);
            qA[nf][1] += __shfl_down_sync(0xffffffffu, qA[nf][1], st);
        }
    }
    if (lane < 4){
        #pragma unroll
        for (int nf = 0; nf < 4; nf++){
            int colL = warpN * 32 + nf * 8 + lane * 2;
            atomicAdd(&bn_s[colL],     sA[nf][0]);
            atomicAdd(&bn_s[colL + 1], sA[nf][1]);
            atomicAdd(&bn_q[colL],     qA[nf][0]);
            atomicAdd(&bn_q[colL + 1], qA[nf][1]);
        }
    }
    __syncthreads();
    if (tid < 64){
        atomicAdd(&g_bns[oBase + tid], bn_s[tid]);
        atomicAdd(&g_bnq[oBase + tid], bn_q[tid]);
    }
}

// ---------------- BN finalize + final --------------------------------------
__global__ void k_bnfin(const float* __restrict__ gamma, const float* __restrict__ beta){
    int o = threadIdx.x;
    float inv = 1.0f / (float)(BB * NN);
    float mean = g_bns[o] * inv;
    float var  = g_bnq[o] * inv - mean * mean;
    float rstd = rsqrtf(var + 1e-5f);
    float sc = gamma[o] * rstd;
    g_scale[o] = sc;
    g_shift[o] = beta[o] - mean * sc;
}
__global__ void k_final(const float* __restrict__ x, float* __restrict__ out){
    size_t i = ((size_t)blockIdx.x * blockDim.x + threadIdx.x) * 4;
    int o = (int)(i & (CC - 1));
    float4 t4 = *(const float4*)(g_t + i);
    float4 x4 = *(const float4*)(x + i);
    float4 sc = *(const float4*)(g_scale + o);
    float4 sh = *(const float4*)(g_shift + o);
    float4 r;
    r.x = x4.x + fmaxf(fmaf(t4.x, sc.x, sh.x), 0.f);
    r.y = x4.y + fmaxf(fmaf(t4.y, sc.y, sh.y), 0.f);
    r.z = x4.z + fmaxf(fmaf(t4.z, sc.z, sh.z), 0.f);
    r.w = x4.w + fmaxf(fmaf(t4.w, sc.w, sh.w), 0.f);
    *(float4*)(out + i) = r;
}

// ---------------- launch ----------------------------------------------------
extern "C" void kernel_launch(void* const* d_in, const int* in_sizes, int n_in,
                              void* d_out, int out_size){
    (void)in_sizes; (void)n_in; (void)out_size;
    const float* x     = (const float*)d_in[1];
    const float* Wq    = (const float*)d_in[2];
    const float* Wv    = (const float*)d_in[3];
    const float* bv    = (const float*)d_in[4];
    const float* Wt    = (const float*)d_in[5];
    const float* bt    = (const float*)d_in[6];
    const float* gamma = (const float*)d_in[7];
    const float* beta  = (const float*)d_in[8];
    float* out = (float*)d_out;

    static cudaStream_t s2 = nullptr;
    static cudaEvent_t eFork = nullptr, eJoin = nullptr;
    if (!s2){
        cudaStreamCreateWithFlags(&s2, cudaStreamNonBlocking);
        cudaEventCreateWithFlags(&eFork, cudaEventDisableTiming);
        cudaEventCreateWithFlags(&eJoin, cudaEventDisableTiming);
        cudaFuncSetAttribute(kt1, cudaFuncAttributeMaxDynamicSharedMemorySize, SDYN);
        cudaFuncSetAttribute(ktG, cudaFuncAttributeMaxDynamicSharedMemorySize, SDYN);
        cudaFuncSetAttribute(ksq, cudaFuncAttributeMaxDynamicSharedMemorySize, SDYN);
        cudaFuncSetAttribute(kt6, cudaFuncAttributeMaxDynamicSharedMemorySize, SDYN);
    }

    k_cvt_x  <<<dim3(64, 4, BB), 256>>>(x);
    k_cvt_w  <<<768, 256>>>(Wq, Wv, Wt);

    // fork: v-projection runs concurrently with the attention chain
    cudaEventRecord(eFork, 0);
    cudaStreamWaitEvent(s2, eFork, 0);
    kt1      <<<dim3(32, 4, BB), 256, SDYN, s2>>>(bv);
    cudaEventRecord(eJoin, s2);

    ktG      <<<dim3(6, 1, 4*BB), 256, SDYN>>>();
    k_gsum   <<<1024, 256>>>();
    ksq      <<<dim3(4, 2, BB), 256, SDYN>>>(0);
    ksq      <<<dim3(4, 2, BB), 256, SDYN>>>(1);
    k_softmax<<<BB*CC, 256>>>();
    k_colsum <<<BB, 256>>>();
    k_scaleWt<<<1024, 256>>>(Wt);
    ksq      <<<dim3(4, 2, BB), 256, SDYN>>>(2);

    cudaStreamWaitEvent(0, eJoin, 0);     // join before fused kt6
    kt6      <<<dim3(32, 4, BB), 256, SDYN>>>(bt);
    k_bnfin  <<<1, 256>>>(gamma, beta);
    k_final  <<<16384, 256>>>(x, out);
}